// round 8
// baseline (speedup 1.0000x reference)
#include <cuda_runtime.h>
#include <cuda_fp16.h>
#include <cstdint>

// ---------------------------------------------------------------------------
// GraphEncoder on GB300 (sm_103a) — fp16 mma.sync pipeline.
//
//   ds[i] = rsqrt(1 + rowsum(A)[i]);   xs = ds∘x  (fp16)
//   Z1  = ds∘(A@xs + xs)                     (agg, N=256)   [= nrm@x]
//   H   = relu(Z1@W1 + b1)                   (feature)
//   P2  = ds∘(H@W2)                          (feature)
//   out = ds∘(A@P2 + P2) + b2                (agg, N=256)
//
// R7: agg GEMMs use fp16-ACCUMULATE HMMA (2x rate vs f32-acc) in K=32 chunks,
// promoted to fp32 registers every chunk. Feature GEMMs unchanged (f32 acc).
// ---------------------------------------------------------------------------

#define DEV_INLINE __device__ __forceinline__

static constexpr int BATCH = 8, NNODE = 4096, INC = 256, HIDC = 512, OUTC = 256;
static constexpr int MT = BATCH * NNODE;   // 32768

// Scratch (allocation-free __device__ globals)
__device__ float  g_ds [MT];                                     // 128 KB
__device__ __half g_Ar [(size_t)BATCH * NNODE * NNODE];          // 256 MB
__device__ __half g_xs [(size_t)MT * INC];                       // 16 MB (plain)
__device__ __half g_xst[(size_t)BATCH * INC * NNODE];            // 16 MB (T, interleaved)
__device__ __half g_Z1 [(size_t)MT * INC];                       // 16 MB (interleaved)
__device__ __half g_H  [(size_t)MT * HIDC];                      // 32 MB (interleaved)
__device__ __half g_P2t[(size_t)BATCH * OUTC * NNODE];           // 16 MB (T, interleaved)
__device__ __half g_P2 [(size_t)MT * OUTC];                      // 16 MB (plain)
__device__ __half g_W1t[HIDC * INC];                             // 256 KB
__device__ __half g_W2t[OUTC * HIDC];                            // 256 KB

// ---------------------------------------------------------------------------
// helpers
// ---------------------------------------------------------------------------
DEV_INLINE int pos8(int p) { return ((p & 3) << 1) | ((p >> 2) & 1); }

DEV_INLINE void cp_async16(uint32_t saddr, const void* gmem) {
    asm volatile("cp.async.cg.shared.global [%0], [%1], 16;" :: "r"(saddr), "l"(gmem));
}
DEV_INLINE void cp_commit() { asm volatile("cp.async.commit_group;"); }
template <int N> DEV_INLINE void cp_wait() { asm volatile("cp.async.wait_group %0;" :: "n"(N)); }

DEV_INLINE uint32_t smem_u32(const void* p) {
    return (uint32_t)__cvta_generic_to_shared(p);
}

DEV_INLINE void lds64(uint32_t& x, uint32_t& y, uint32_t addr) {
    asm volatile("ld.shared.v2.b32 {%0, %1}, [%2];" : "=r"(x), "=r"(y) : "r"(addr));
}

// f32-accumulate HMMA (feature GEMMs)
DEV_INLINE void mma_f16(float* d, const uint32_t* a, const uint32_t* b) {
    asm volatile(
        "mma.sync.aligned.m16n8k16.row.col.f32.f16.f16.f32 "
        "{%0,%1,%2,%3},{%4,%5,%6,%7},{%8,%9},{%0,%1,%2,%3};"
        : "+f"(d[0]), "+f"(d[1]), "+f"(d[2]), "+f"(d[3])
        : "r"(a[0]), "r"(a[1]), "r"(a[2]), "r"(a[3]), "r"(b[0]), "r"(b[1]));
}

// f16-accumulate HMMA (agg GEMMs): d = a*b + c
DEV_INLINE void mma_f16h(uint32_t* d, const uint32_t* a, const uint32_t* b,
                         uint32_t c0, uint32_t c1) {
    asm volatile(
        "mma.sync.aligned.m16n8k16.row.col.f16.f16.f16.f16 "
        "{%0,%1},{%2,%3,%4,%5},{%6,%7},{%8,%9};"
        : "=r"(d[0]), "=r"(d[1])
        : "r"(a[0]), "r"(a[1]), "r"(a[2]), "r"(a[3]),
          "r"(b[0]), "r"(b[1]), "r"(c0), "r"(c1));
}

// ---------------------------------------------------------------------------
// prep_A: ds[row] = rsqrt(1+rowsum), Ar = fp16(A) pair-interleaved K-major
// ---------------------------------------------------------------------------
__global__ void __launch_bounds__(256) prep_A_kernel(const float* __restrict__ A,
                                                     __half* __restrict__ Ar,
                                                     float* __restrict__ ds) {
    __shared__ float srow[NNODE];
    long long row = blockIdx.x;
    const float4* p = (const float4*)(A + row * (long long)NNODE);
    float s = 0.f;
    #pragma unroll 2
    for (int i = threadIdx.x; i < NNODE / 4; i += 256) {
        float4 v = p[i];
        s += (v.x + v.y) + (v.z + v.w);
        *(float4*)(srow + 4 * i) = v;
    }
    #pragma unroll
    for (int o = 16; o; o >>= 1) s += __shfl_xor_sync(0xFFFFFFFFu, s, o);
    __shared__ float ws[8];
    if ((threadIdx.x & 31) == 0) ws[threadIdx.x >> 5] = s;
    __syncthreads();
    if (threadIdx.x == 0) {
        float tot = 0.f;
        #pragma unroll
        for (int i = 0; i < 8; i++) tot += ws[i];
        ds[row] = rsqrtf(tot + 1.0f);
    }
    int g = threadIdx.x;                  // 256 groups of 16 halfs
    const float* src = srow + 16 * g;
    __half2 ph[8];
    #pragma unroll
    for (int pp = 0; pp < 8; pp++)
        ph[pos8(pp)] = __floats2half2_rn(src[2 * pp], src[2 * pp + 1]);
    uint4* dst = (uint4*)(Ar + row * (long long)NNODE + 16 * g);
    dst[0] = *(uint4*)&ph[0];
    dst[1] = *(uint4*)&ph[4];
}

// ---------------------------------------------------------------------------
// prep_x: xs = fp16(ds∘x) plain row-major; xst = transposed, pair-interleaved
// ---------------------------------------------------------------------------
__global__ void __launch_bounds__(256) prep_x_kernel(const float* __restrict__ x,
                                                     const float* __restrict__ ds,
                                                     __half* __restrict__ xs,
                                                     __half* __restrict__ xst) {
    __shared__ __half sm[32][34];
    int m0 = blockIdx.x * 32, c0 = blockIdx.y * 32, b = blockIdx.z;
    #pragma unroll
    for (int r4 = 0; r4 < 4; r4++) {
        int idx = threadIdx.x + r4 * 256;
        int im = idx >> 5, ic = idx & 31;
        long long gm = (long long)b * NNODE + m0 + im;
        float v = x[gm * INC + c0 + ic] * ds[gm];
        __half h = __float2half_rn(v);
        sm[im][ic] = h;
        xs[gm * INC + c0 + ic] = h;
    }
    __syncthreads();
    #pragma unroll
    for (int r2 = 0; r2 < 2; r2++) {
        int pidx = threadIdx.x + r2 * 256;
        int jc = pidx >> 4, lp = pidx & 15;
        int grp = lp >> 3, pp = lp & 7;
        int mA = grp * 16 + 2 * pp;
        __half2 hv = __halves2half2(sm[mA][jc], sm[mA + 1][jc]);
        long long dst = (long long)b * INC * NNODE + (long long)(c0 + jc) * NNODE
                      + m0 + grp * 16 + pos8(pp) * 2;
        *(__half2*)(xst + dst) = hv;
    }
}

// ---------------------------------------------------------------------------
// prep_W: Wt[n][k-interleaved] = fp16(W[k][n])
// ---------------------------------------------------------------------------
__global__ void __launch_bounds__(256) prep_W_kernel(const float* __restrict__ W,
                                                     __half* __restrict__ Wt,
                                                     int K, int N) {
    int id = blockIdx.x * 256 + threadIdx.x;
    if (id >= N * (K / 2)) return;
    int n = id / (K / 2), pk = id % (K / 2);
    int grp = pk >> 3, pp = pk & 7;
    int k = 2 * pk;
    __half2 hv = __floats2half2_rn(W[(long long)k * N + n], W[(long long)(k + 1) * N + n]);
    *(__half2*)(Wt + (long long)n * K + grp * 16 + pos8(pp) * 2) = hv;
}

// ===========================================================================
// WIDE agg GEMM: C = A(MxK) @ B(NxK)^T, CTA 128x256, 8 warps of 64x64, BK=64,
// 4-stage ring (192KB), occ 1. fp16-accumulate MMA in K=32 chunks, promoted
// to fp32 registers per chunk.
//   EPI 0: Z1[m][n] = ds[m]*(acc + self[m][n])      -> half interleaved
//   EPI 3: out[m][n] = ds[m]*(acc + self[m][n]) + bias[n]  -> fp32
// ===========================================================================
static constexpr int WSTAGE = 49152;                 // A 16KB + B 32KB
static constexpr int WSMEM  = 4 * WSTAGE;            // 192 KB

template <int EPI>
__global__ void __launch_bounds__(256, 1) gemm_f16_wide(
    const __half* __restrict__ Ag, const __half* __restrict__ Bg, void* __restrict__ Cg,
    const __half* __restrict__ selfg, const float* __restrict__ ds,
    const float* __restrict__ bias,
    int K, long long lda, long long ldb, long long ldc, long long ldself,
    long long sAb, long long sBb, long long sCb, long long sSelfb) {

    extern __shared__ char smem[];
    const uint32_t sbase = smem_u32(smem);

    const int tid = threadIdx.x;
    const int b = blockIdx.z;
    const long long m0 = (long long)blockIdx.y * 128;
    const int n0 = blockIdx.x * 256;

    const __half* Ab = Ag + (long long)b * sAb;
    const __half* Bb = Bg + (long long)b * sBb;

    const int warp = tid >> 5, lane = tid & 31;
    const int gr = lane >> 2, t = lane & 3;
    const int mW = (warp >> 2) * 64, nW = (warp & 3) * 64;

    float acc[4][8][4];
    #pragma unroll
    for (int mi = 0; mi < 4; mi++)
        #pragma unroll
        for (int ni = 0; ni < 8; ni++)
            #pragma unroll
            for (int e = 0; e < 4; e++) acc[mi][ni][e] = 0.f;

    auto load_tile = [&](int st, int kt) {
        uint32_t sa = sbase + st * WSTAGE;
        #pragma unroll
        for (int i = 0; i < 4; i++) {                       // A: 1024 chunks
            int cq = tid + i * 256;
            int r = cq >> 3, c = cq & 7;
            const __half* g = Ab + (m0 + r) * lda + kt + c * 8;
            cp_async16(sa + r * 128 + ((c ^ (r & 7)) << 4), g);
        }
        uint32_t sb = sa + 16384;
        #pragma unroll
        for (int i = 0; i < 8; i++) {                       // B: 2048 chunks
            int cq = tid + i * 256;
            int r = cq >> 3, c = cq & 7;
            const __half* g = Bb + (long long)(n0 + r) * ldb + kt + c * 8;
            cp_async16(sb + r * 128 + ((c ^ (r & 7)) << 4), g);
        }
    };

    const int nK = K / 64;
    load_tile(0, 0); cp_commit();
    load_tile(1, 64); cp_commit();
    load_tile(2, 128); cp_commit();

    for (int tt = 0; tt < nK; tt++) {
        int rem = nK - 1 - tt;
        if (rem >= 2) cp_wait<2>(); else if (rem == 1) cp_wait<1>(); else cp_wait<0>();
        __syncthreads();
        if (tt + 3 < nK) { load_tile((tt + 3) & 3, (tt + 3) * 64); cp_commit(); }

        uint32_t sa = sbase + (tt & 3) * WSTAGE;
        uint32_t sb = sa + 16384;

        // two K=32 chunks per K-iter; each chunk: 2 G-steps of K=16 in fp16 acc
        #pragma unroll
        for (int gp = 0; gp < 2; gp++) {
            uint32_t a[2][4][4];
            uint32_t swo[2];
            #pragma unroll
            for (int g2 = 0; g2 < 2; g2++) {
                const int G = gp * 2 + g2;
                const int chunk = (G << 1) | (t >> 1);
                swo[g2] = ((chunk ^ gr) << 4) + ((t & 1) << 3);
                #pragma unroll
                for (int mi = 0; mi < 4; mi++) {
                    uint32_t ra = sa + (mW + mi * 16 + gr) * 128 + swo[g2];
                    lds64(a[g2][mi][0], a[g2][mi][2], ra);
                    lds64(a[g2][mi][1], a[g2][mi][3], ra + 1024);
                }
            }
            #pragma unroll
            for (int ni = 0; ni < 8; ni++) {
                uint32_t b0[2], b1[2];
                uint32_t rb = sb + (nW + ni * 8 + gr) * 128;
                lds64(b0[0], b0[1], rb + swo[0]);
                lds64(b1[0], b1[1], rb + swo[1]);
                uint32_t ch[4][2];
                #pragma unroll
                for (int mi = 0; mi < 4; mi++)
                    mma_f16h(ch[mi], a[0][mi], b0, 0u, 0u);
                #pragma unroll
                for (int mi = 0; mi < 4; mi++)
                    mma_f16h(ch[mi], a[1][mi], b1, ch[mi][0], ch[mi][1]);
                // promote chunk to fp32
                #pragma unroll
                for (int mi = 0; mi < 4; mi++) {
                    float2 f0 = __half22float2(*reinterpret_cast<__half2*>(&ch[mi][0]));
                    float2 f1 = __half22float2(*reinterpret_cast<__half2*>(&ch[mi][1]));
                    acc[mi][ni][0] += f0.x;
                    acc[mi][ni][1] += f0.y;
                    acc[mi][ni][2] += f1.x;
                    acc[mi][ni][3] += f1.y;
                }
            }
        }
    }
    __syncthreads();

    // ---------------- epilogue ----------------
    const __half* selfb = selfg + (long long)b * sSelfb;
    #pragma unroll
    for (int mi = 0; mi < 4; mi++) {
        #pragma unroll
        for (int rr = 0; rr < 2; rr++) {
            int m_loc = mW + mi * 16 + gr + rr * 8;
            long long m = m0 + m_loc;
            float d = ds[(long long)b * NNODE + m];
            #pragma unroll
            for (int ni = 0; ni < 8; ni++) {
                int col = n0 + nW + ni * 8 + 2 * t;
                float v0 = acc[mi][ni][rr * 2 + 0];
                float v1 = acc[mi][ni][rr * 2 + 1];
                float2 sv = __half22float2(*(const __half2*)(selfb + m * ldself + col));
                if (EPI == 0) {
                    v0 = d * (v0 + sv.x);
                    v1 = d * (v1 + sv.y);
                    int g16 = col >> 4, lp = (col >> 1) & 7;
                    __half* Ch = (__half*)Cg + (long long)b * sCb;
                    *(__half2*)(Ch + m * ldc + (g16 << 4) + (pos8(lp) << 1)) =
                        __floats2half2_rn(v0, v1);
                } else {  // EPI == 3
                    v0 = fmaf(d, v0 + sv.x, bias[col]);
                    v1 = fmaf(d, v1 + sv.y, bias[col + 1]);
                    float* Cf = (float*)Cg + (long long)b * sCb;
                    *(float2*)(Cf + m * ldc + col) = make_float2(v0, v1);
                }
            }
        }
    }
}

// ===========================================================================
// NARROW feature GEMM (f32 acc): CTA 128x128, 4 warps, 2-stage, occ 3.
//   EPI 1: H = relu(acc+bias) -> half interleaved.
//   EPI 2: P2t[n][m] = ds[m]*acc (T+interleave) ; P2[m][n] plain.
// ===========================================================================
static constexpr int STAGE_BYTES = 32768;
static constexpr int SMEM_BYTES = 2 * STAGE_BYTES;     // 64 KB

template <int EPI>
__global__ void __launch_bounds__(128, 3) gemm_f16(
    const __half* __restrict__ Ag, const __half* __restrict__ Bg, void* __restrict__ Cg,
    const float* __restrict__ ds, const float* __restrict__ bias,
    __half* __restrict__ C2g,
    int K, long long lda, long long ldb, long long ldc) {

    extern __shared__ char smem[];
    const uint32_t sbase = smem_u32(smem);

    const int tid = threadIdx.x;
    const long long m0 = (long long)blockIdx.y * 128;
    const int n0 = blockIdx.x * 128;

    const __half* Ab = Ag;
    const __half* Bb = Bg;

    const int warp = tid >> 5, lane = tid & 31;
    const int gr = lane >> 2, t = lane & 3;
    const int mW = (warp >> 1) * 64, nW = (warp & 1) * 64;

    float acc[4][8][4];
    #pragma unroll
    for (int mi = 0; mi < 4; mi++)
        #pragma unroll
        for (int ni = 0; ni < 8; ni++)
            #pragma unroll
            for (int e = 0; e < 4; e++) acc[mi][ni][e] = 0.f;

    auto load_tile = [&](int st, int kt) {
        uint32_t sa = sbase + st * STAGE_BYTES;
        #pragma unroll
        for (int i = 0; i < 8; i++) {
            int cq = tid + i * 128;
            int r = cq >> 3, c = cq & 7;
            const __half* g = Ab + (m0 + r) * lda + kt + c * 8;
            cp_async16(sa + r * 128 + ((c ^ (r & 7)) << 4), g);
        }
        uint32_t sb = sa + 16384;
        #pragma unroll
        for (int i = 0; i < 8; i++) {
            int cq = tid + i * 128;
            int r = cq >> 3, c = cq & 7;
            const __half* g = Bb + (long long)(n0 + r) * ldb + kt + c * 8;
            cp_async16(sb + r * 128 + ((c ^ (r & 7)) << 4), g);
        }
    };

    const int nK = K / 64;
    load_tile(0, 0); cp_commit();

    for (int tt = 0; tt < nK; tt++) {
        if (tt + 1 < nK) { load_tile((tt + 1) & 1, (tt + 1) * 64); cp_commit(); cp_wait<1>(); }
        else cp_wait<0>();
        __syncthreads();

        uint32_t sa = sbase + (tt & 1) * STAGE_BYTES;
        uint32_t sb = sa + 16384;

        #pragma unroll
        for (int G = 0; G < 4; G++) {
            const int chunk = (G << 1) | (t >> 1);
            const uint32_t swo = ((chunk ^ gr) << 4) + ((t & 1) << 3);
            uint32_t a[4][4];
            #pragma unroll
            for (int mi = 0; mi < 4; mi++) {
                uint32_t ra = sa + (mW + mi * 16 + gr) * 128 + swo;
                lds64(a[mi][0], a[mi][2], ra);
                lds64(a[mi][1], a[mi][3], ra + 1024);
            }
            #pragma unroll
            for (int ni = 0; ni < 8; ni++) {
                uint32_t bf[2];
                lds64(bf[0], bf[1], sb + (nW + ni * 8 + gr) * 128 + swo);
                #pragma unroll
                for (int mi = 0; mi < 4; mi++)
                    mma_f16(acc[mi][ni], a[mi], bf);
            }
        }
        __syncthreads();
    }

    if (EPI == 2) {
        __half* sT = (__half*)smem;
        const long long gmb = (long long)blockIdx.y * 128;
        #pragma unroll
        for (int mi = 0; mi < 4; mi++) {
            #pragma unroll
            for (int rr = 0; rr < 2; rr++) {
                int m_loc = mW + mi * 16 + gr + rr * 8;
                long long gm = gmb + m_loc;
                float d = ds[gm];
                #pragma unroll
                for (int ni = 0; ni < 8; ni++) {
                    int n_loc = nW + ni * 8 + 2 * t;
                    float v0 = d * acc[mi][ni][rr * 2 + 0];
                    float v1 = d * acc[mi][ni][rr * 2 + 1];
                    __half2 hv = __floats2half2_rn(v0, v1);
                    *(__half2*)(sT + m_loc * 136 + n_loc) = hv;
                    *(__half2*)(C2g + gm * ldc + n0 + n_loc) = hv;   // P2 plain
                }
            }
        }
        __syncthreads();
        int bo = (int)(gmb >> 12);
        long long m0loc = gmb & 4095;
        __half* Ct = (__half*)Cg + (long long)bo * OUTC * NNODE
                   + (long long)(n0 + tid) * NNODE + m0loc;
        #pragma unroll
        for (int mg = 0; mg < 8; mg++) {
            __half2 ph[8];
            #pragma unroll
            for (int pp = 0; pp < 8; pp++) {
                int mA = mg * 16 + 2 * pp;
                ph[pos8(pp)] = __halves2half2(sT[mA * 136 + tid], sT[(mA + 1) * 136 + tid]);
            }
            uint4* dst = (uint4*)(Ct + mg * 16);
            dst[0] = *(uint4*)&ph[0];
            dst[1] = *(uint4*)&ph[4];
        }
        return;
    }

    // EPI == 1
    #pragma unroll
    for (int mi = 0; mi < 4; mi++) {
        #pragma unroll
        for (int rr = 0; rr < 2; rr++) {
            int m_loc = mW + mi * 16 + gr + rr * 8;
            long long m = m0 + m_loc;
            #pragma unroll
            for (int ni = 0; ni < 8; ni++) {
                int col = n0 + nW + ni * 8 + 2 * t;
                float v0 = fmaxf(acc[mi][ni][rr * 2 + 0] + bias[col], 0.f);
                float v1 = fmaxf(acc[mi][ni][rr * 2 + 1] + bias[col + 1], 0.f);
                int g16 = col >> 4, lp = (col >> 1) & 7;
                __half* Ch = (__half*)Cg;
                *(__half2*)(Ch + m * ldc + (g16 << 4) + (pos8(lp) << 1)) =
                    __floats2half2_rn(v0, v1);
            }
        }
    }
}

// ---------------------------------------------------------------------------
// launch
// ---------------------------------------------------------------------------
extern "C" void kernel_launch(void* const* d_in, const int* in_sizes, int n_in,
                              void* d_out, int out_size) {
    const float* x  = (const float*)d_in[0];
    const float* A  = (const float*)d_in[1];
    const float* W1 = (const float*)d_in[2];
    const float* b1 = (const float*)d_in[3];
    const float* W2 = (const float*)d_in[4];
    const float* b2 = (const float*)d_in[5];
    float* out = (float*)d_out;

    float* ds;
    __half *Ar, *xs, *xst, *Z1, *H, *P2t, *P2, *W1t, *W2t;
    cudaGetSymbolAddress((void**)&ds,  g_ds);
    cudaGetSymbolAddress((void**)&Ar,  g_Ar);
    cudaGetSymbolAddress((void**)&xs,  g_xs);
    cudaGetSymbolAddress((void**)&xst, g_xst);
    cudaGetSymbolAddress((void**)&Z1,  g_Z1);
    cudaGetSymbolAddress((void**)&H,   g_H);
    cudaGetSymbolAddress((void**)&P2t, g_P2t);
    cudaGetSymbolAddress((void**)&P2,  g_P2);
    cudaGetSymbolAddress((void**)&W1t, g_W1t);
    cudaGetSymbolAddress((void**)&W2t, g_W2t);

    cudaFuncSetAttribute(gemm_f16_wide<0>, cudaFuncAttributeMaxDynamicSharedMemorySize, WSMEM);
    cudaFuncSetAttribute(gemm_f16_wide<3>, cudaFuncAttributeMaxDynamicSharedMemorySize, WSMEM);
    cudaFuncSetAttribute(gemm_f16<1>, cudaFuncAttributeMaxDynamicSharedMemorySize, SMEM_BYTES);
    cudaFuncSetAttribute(gemm_f16<2>, cudaFuncAttributeMaxDynamicSharedMemorySize, SMEM_BYTES);

    // prep
    prep_A_kernel<<<BATCH * NNODE, 256>>>(A, Ar, ds);
    prep_x_kernel<<<dim3(NNODE / 32, INC / 32, BATCH), 256>>>(x, ds, xs, xst);
    prep_W_kernel<<<(HIDC * (INC / 2) + 255) / 256, 256>>>(W1, W1t, INC, HIDC);
    prep_W_kernel<<<(OUTC * (HIDC / 2) + 255) / 256, 256>>>(W2, W2t, HIDC, OUTC);

    // G1: Z1 = ds∘(A@xs + xs)   (wide agg, fp16-acc chunks)
    gemm_f16_wide<0><<<dim3(INC / 256, NNODE / 128, BATCH), 256, WSMEM>>>(
        Ar, xst, Z1, xs, ds, nullptr,
        NNODE, NNODE, NNODE, INC, INC,
        (long long)NNODE * NNODE, (long long)INC * NNODE,
        (long long)NNODE * INC, (long long)NNODE * INC);

    // G2: H = relu(Z1@W1 + b1)
    gemm_f16<1><<<dim3(HIDC / 128, MT / 128, 1), 128, SMEM_BYTES>>>(
        Z1, W1t, H, ds, b1, nullptr, INC, INC, INC, HIDC);

    // G3: P2t = (ds∘(H@W2))^T + P2 plain copy
    gemm_f16<2><<<dim3(OUTC / 128, MT / 128, 1), 128, SMEM_BYTES>>>(
        H, W2t, P2t, ds, nullptr, P2, HIDC, HIDC, HIDC, OUTC);

    // G4: out = ds∘(A@P2 + P2) + b2   (wide agg, fp16-acc chunks)
    gemm_f16_wide<3><<<dim3(OUTC / 256, NNODE / 128, BATCH), 256, WSMEM>>>(
        Ar, P2t, out, P2, ds, b2,
        NNODE, NNODE, NNODE, OUTC, OUTC,
        (long long)NNODE * NNODE, (long long)OUTC * NNODE,
        (long long)NNODE * OUTC, (long long)NNODE * OUTC);
}

// round 9
// speedup vs baseline: 1.0156x; 1.0156x over previous
#include <cuda_runtime.h>
#include <cuda_fp16.h>
#include <cstdint>

// ---------------------------------------------------------------------------
// GraphEncoder on GB300 (sm_103a) — fp16 mma.sync pipeline.
//
//   ds[i] = rsqrt(1 + rowsum(A)[i]);   xs = ds∘x  (fp16)
//   Z1  = ds∘(A@xs + xs)                     (agg, N=256)   [= nrm@x]
//   H   = relu(Z1@W1 + b1)                   (feature)
//   P2  = ds∘(H@W2)                          (feature)
//   out = ds∘(A@P2 + P2) + b2                (agg, N=256)
//
// R8: agg GEMMs = R6 wide kernel (f32-acc HMMA, 95% of its ceiling) + tail
// split-K-4: 148 full-K CTAs (wave 1) + 108 tail tiles x 4 quarter-K CTAs
// writing fp32 partials to scratch; 4th arriver reduces + runs epilogue.
// Removes the 13.5% wave-quantization idle per agg.
// ---------------------------------------------------------------------------

#define DEV_INLINE __device__ __forceinline__

static constexpr int BATCH = 8, NNODE = 4096, INC = 256, HIDC = 512, OUTC = 256;
static constexpr int MT = BATCH * NNODE;   // 32768

static constexpr int TILES      = 256;   // per agg: 8 batches x 32 m-tiles
static constexpr int FULL_TILES = 148;   // one exact wave of full-K CTAs
static constexpr int TAIL_TILES = TILES - FULL_TILES;   // 108
static constexpr int TILE_ELEMS = 128 * 256;            // 32768 fp32

// Scratch (allocation-free __device__ globals)
__device__ float  g_ds  [MT];
__device__ __half g_Ar  [(size_t)BATCH * NNODE * NNODE];          // 256 MB
__device__ __half g_xs  [(size_t)MT * INC];                       // plain
__device__ __half g_xst [(size_t)BATCH * INC * NNODE];            // T, interleaved
__device__ __half g_Z1  [(size_t)MT * INC];                       // interleaved
__device__ __half g_H   [(size_t)MT * HIDC];                      // interleaved
__device__ __half g_P2t [(size_t)BATCH * OUTC * NNODE];           // T, interleaved
__device__ __half g_P2  [(size_t)MT * OUTC];                      // plain
__device__ __half g_W1t [HIDC * INC];
__device__ __half g_W2t [OUTC * HIDC];
__device__ float  g_scr1[(size_t)TAIL_TILES * 4 * TILE_ELEMS];    // 56.6 MB
__device__ float  g_scr2[(size_t)TAIL_TILES * 4 * TILE_ELEMS];    // 56.6 MB
__device__ int    g_cnt1[TAIL_TILES];                             // zero-init
__device__ int    g_cnt2[TAIL_TILES];                             // zero-init

// ---------------------------------------------------------------------------
// helpers
// ---------------------------------------------------------------------------
DEV_INLINE int pos8(int p) { return ((p & 3) << 1) | ((p >> 2) & 1); }

DEV_INLINE void cp_async16(uint32_t saddr, const void* gmem) {
    asm volatile("cp.async.cg.shared.global [%0], [%1], 16;" :: "r"(saddr), "l"(gmem));
}
DEV_INLINE void cp_commit() { asm volatile("cp.async.commit_group;"); }
template <int N> DEV_INLINE void cp_wait() { asm volatile("cp.async.wait_group %0;" :: "n"(N)); }

DEV_INLINE uint32_t smem_u32(const void* p) {
    return (uint32_t)__cvta_generic_to_shared(p);
}

DEV_INLINE void lds64(uint32_t& x, uint32_t& y, uint32_t addr) {
    asm volatile("ld.shared.v2.b32 {%0, %1}, [%2];" : "=r"(x), "=r"(y) : "r"(addr));
}

DEV_INLINE void mma_f16(float* d, const uint32_t* a, const uint32_t* b) {
    asm volatile(
        "mma.sync.aligned.m16n8k16.row.col.f32.f16.f16.f32 "
        "{%0,%1,%2,%3},{%4,%5,%6,%7},{%8,%9},{%0,%1,%2,%3};"
        : "+f"(d[0]), "+f"(d[1]), "+f"(d[2]), "+f"(d[3])
        : "r"(a[0]), "r"(a[1]), "r"(a[2]), "r"(a[3]), "r"(b[0]), "r"(b[1]));
}

// ---------------------------------------------------------------------------
// prep_A: ds[row] = rsqrt(1+rowsum), Ar = fp16(A) pair-interleaved K-major
// ---------------------------------------------------------------------------
__global__ void __launch_bounds__(256) prep_A_kernel(const float* __restrict__ A,
                                                     __half* __restrict__ Ar,
                                                     float* __restrict__ ds) {
    __shared__ float srow[NNODE];
    long long row = blockIdx.x;
    const float4* p = (const float4*)(A + row * (long long)NNODE);
    float s = 0.f;
    #pragma unroll 2
    for (int i = threadIdx.x; i < NNODE / 4; i += 256) {
        float4 v = p[i];
        s += (v.x + v.y) + (v.z + v.w);
        *(float4*)(srow + 4 * i) = v;
    }
    #pragma unroll
    for (int o = 16; o; o >>= 1) s += __shfl_xor_sync(0xFFFFFFFFu, s, o);
    __shared__ float ws[8];
    if ((threadIdx.x & 31) == 0) ws[threadIdx.x >> 5] = s;
    __syncthreads();
    if (threadIdx.x == 0) {
        float tot = 0.f;
        #pragma unroll
        for (int i = 0; i < 8; i++) tot += ws[i];
        ds[row] = rsqrtf(tot + 1.0f);
    }
    int g = threadIdx.x;                  // 256 groups of 16 halfs
    const float* src = srow + 16 * g;
    __half2 ph[8];
    #pragma unroll
    for (int pp = 0; pp < 8; pp++)
        ph[pos8(pp)] = __floats2half2_rn(src[2 * pp], src[2 * pp + 1]);
    uint4* dst = (uint4*)(Ar + row * (long long)NNODE + 16 * g);
    dst[0] = *(uint4*)&ph[0];
    dst[1] = *(uint4*)&ph[4];
}

// ---------------------------------------------------------------------------
// prep_x: xs = fp16(ds∘x) plain row-major; xst = transposed, pair-interleaved
// ---------------------------------------------------------------------------
__global__ void __launch_bounds__(256) prep_x_kernel(const float* __restrict__ x,
                                                     const float* __restrict__ ds,
                                                     __half* __restrict__ xs,
                                                     __half* __restrict__ xst) {
    __shared__ __half sm[32][34];
    int m0 = blockIdx.x * 32, c0 = blockIdx.y * 32, b = blockIdx.z;
    #pragma unroll
    for (int r4 = 0; r4 < 4; r4++) {
        int idx = threadIdx.x + r4 * 256;
        int im = idx >> 5, ic = idx & 31;
        long long gm = (long long)b * NNODE + m0 + im;
        float v = x[gm * INC + c0 + ic] * ds[gm];
        __half h = __float2half_rn(v);
        sm[im][ic] = h;
        xs[gm * INC + c0 + ic] = h;
    }
    __syncthreads();
    #pragma unroll
    for (int r2 = 0; r2 < 2; r2++) {
        int pidx = threadIdx.x + r2 * 256;
        int jc = pidx >> 4, lp = pidx & 15;
        int grp = lp >> 3, pp = lp & 7;
        int mA = grp * 16 + 2 * pp;
        __half2 hv = __halves2half2(sm[mA][jc], sm[mA + 1][jc]);
        long long dst = (long long)b * INC * NNODE + (long long)(c0 + jc) * NNODE
                      + m0 + grp * 16 + pos8(pp) * 2;
        *(__half2*)(xst + dst) = hv;
    }
}

// ---------------------------------------------------------------------------
// prep_W: Wt[n][k-interleaved] = fp16(W[k][n])
// ---------------------------------------------------------------------------
__global__ void __launch_bounds__(256) prep_W_kernel(const float* __restrict__ W,
                                                     __half* __restrict__ Wt,
                                                     int K, int N) {
    int id = blockIdx.x * 256 + threadIdx.x;
    if (id >= N * (K / 2)) return;
    int n = id / (K / 2), pk = id % (K / 2);
    int grp = pk >> 3, pp = pk & 7;
    int k = 2 * pk;
    __half2 hv = __floats2half2_rn(W[(long long)k * N + n], W[(long long)(k + 1) * N + n]);
    *(__half2*)(Wt + (long long)n * K + grp * 16 + pos8(pp) * 2) = hv;
}

// ===========================================================================
// AGG GEMM with tail split-K:
//   C(b) = Ar(b)[4096x4096] @ Bt(b)[256x4096]^T, tiles of 128 rows.
//   bid < 148          : full-K tile bid, normal epilogue.
//   bid >= 148         : quarter-K (1024) of tile 148+(q>>2); partial fp32 ->
//                        scr[(tile-148)*4+kq]; 4th arriver reduces+epilogues.
//   EPI 0: Z1[m][n] = ds[m]*(acc + self[m][n])      -> half interleaved
//   EPI 3: out[m][n] = ds[m]*(acc + self[m][n]) + bias[n]  -> fp32
// ===========================================================================
static constexpr int WSTAGE = 49152;                 // A 16KB + B 32KB
static constexpr int WSMEM  = 4 * WSTAGE;            // 192 KB

template <int EPI>
__global__ void __launch_bounds__(256, 1) gemm_agg(
    const __half* __restrict__ Ag, const __half* __restrict__ Bg, void* __restrict__ Cg,
    const __half* __restrict__ selfg, const float* __restrict__ ds,
    const float* __restrict__ bias, float* __restrict__ scr, int* __restrict__ cnt) {

    extern __shared__ char smem[];
    const uint32_t sbase = smem_u32(smem);
    const int tid = threadIdx.x;

    // ---- tile / K-range decode ----
    int bid = blockIdx.x;
    int tile, kq, iters, k0;
    if (bid < FULL_TILES) { tile = bid; kq = -1; k0 = 0; iters = 64; }
    else {
        int q = bid - FULL_TILES;
        tile = FULL_TILES + (q >> 2);
        kq = q & 3;
        k0 = kq * 1024;
        iters = 16;
    }
    const int b = tile >> 5;                 // batch
    const int m0 = (tile & 31) * 128;        // row block within batch

    const __half* Ab = Ag + (size_t)b * NNODE * NNODE;
    const __half* Bb = Bg + (size_t)b * 256 * NNODE;
    const __half* selfb = selfg + (size_t)b * NNODE * 256;

    const int warp = tid >> 5, lane = tid & 31;
    const int gr = lane >> 2, t = lane & 3;
    const int mW = (warp >> 2) * 64, nW = (warp & 3) * 64;

    float acc[4][8][4];
    #pragma unroll
    for (int mi = 0; mi < 4; mi++)
        #pragma unroll
        for (int ni = 0; ni < 8; ni++)
            #pragma unroll
            for (int e = 0; e < 4; e++) acc[mi][ni][e] = 0.f;

    auto load_tile = [&](int st, int kt) {
        uint32_t sa = sbase + st * WSTAGE;
        #pragma unroll
        for (int i = 0; i < 4; i++) {                       // A: 1024 chunks
            int cq = tid + i * 256;
            int r = cq >> 3, c = cq & 7;
            const __half* g = Ab + (size_t)(m0 + r) * NNODE + kt + c * 8;
            cp_async16(sa + r * 128 + ((c ^ (r & 7)) << 4), g);
        }
        uint32_t sb = sa + 16384;
        #pragma unroll
        for (int i = 0; i < 8; i++) {                       // B: 2048 chunks
            int cq = tid + i * 256;
            int r = cq >> 3, c = cq & 7;
            const __half* g = Bb + (size_t)r * NNODE + kt + c * 8;
            cp_async16(sb + r * 128 + ((c ^ (r & 7)) << 4), g);
        }
    };

    load_tile(0, k0); cp_commit();
    load_tile(1, k0 + 64); cp_commit();
    load_tile(2, k0 + 128); cp_commit();

    for (int tt = 0; tt < iters; tt++) {
        int rem = iters - 1 - tt;
        if (rem >= 2) cp_wait<2>(); else if (rem == 1) cp_wait<1>(); else cp_wait<0>();
        __syncthreads();
        if (tt + 3 < iters) { load_tile((tt + 3) & 3, k0 + (tt + 3) * 64); cp_commit(); }

        uint32_t sa = sbase + (tt & 3) * WSTAGE;
        uint32_t sb = sa + 16384;

        #pragma unroll
        for (int G = 0; G < 4; G++) {
            const int chunk = (G << 1) | (t >> 1);
            const uint32_t swo = ((chunk ^ gr) << 4) + ((t & 1) << 3);
            uint32_t a[4][4];
            #pragma unroll
            for (int mi = 0; mi < 4; mi++) {
                uint32_t ra = sa + (mW + mi * 16 + gr) * 128 + swo;
                lds64(a[mi][0], a[mi][2], ra);
                lds64(a[mi][1], a[mi][3], ra + 1024);
            }
            #pragma unroll
            for (int ni = 0; ni < 8; ni++) {
                uint32_t bf[2];
                lds64(bf[0], bf[1], sb + (nW + ni * 8 + gr) * 128 + swo);
                #pragma unroll
                for (int mi = 0; mi < 4; mi++)
                    mma_f16(acc[mi][ni], a[mi], bf);
            }
        }
    }
    __syncthreads();

    if (kq < 0) {
        // ---------------- full-K epilogue ----------------
        #pragma unroll
        for (int mi = 0; mi < 4; mi++) {
            #pragma unroll
            for (int rr = 0; rr < 2; rr++) {
                int m_loc = mW + mi * 16 + gr + rr * 8;
                long long m = m0 + m_loc;
                float d = ds[(long long)b * NNODE + m];
                #pragma unroll
                for (int ni = 0; ni < 8; ni++) {
                    int col = nW + ni * 8 + 2 * t;
                    float v0 = acc[mi][ni][rr * 2 + 0];
                    float v1 = acc[mi][ni][rr * 2 + 1];
                    float2 sv = __half22float2(*(const __half2*)(selfb + m * 256 + col));
                    if (EPI == 0) {
                        v0 = d * (v0 + sv.x);
                        v1 = d * (v1 + sv.y);
                        int g16 = col >> 4, lp = (col >> 1) & 7;
                        __half* Ch = (__half*)Cg + (size_t)b * NNODE * 256;
                        *(__half2*)(Ch + m * 256 + (g16 << 4) + (pos8(lp) << 1)) =
                            __floats2half2_rn(v0, v1);
                    } else {
                        v0 = fmaf(d, v0 + sv.x, bias[col]);
                        v1 = fmaf(d, v1 + sv.y, bias[col + 1]);
                        float* Cf = (float*)Cg + (size_t)b * NNODE * 256;
                        *(float2*)(Cf + m * 256 + col) = make_float2(v0, v1);
                    }
                }
            }
        }
        return;
    }

    // ---------------- tail: store partial, last arriver reduces ----------------
    const int tl = tile - FULL_TILES;
    float* my = scr + ((size_t)tl * 4 + kq) * TILE_ELEMS;
    #pragma unroll
    for (int mi = 0; mi < 4; mi++) {
        #pragma unroll
        for (int rr = 0; rr < 2; rr++) {
            int m_loc = mW + mi * 16 + gr + rr * 8;
            #pragma unroll
            for (int ni = 0; ni < 8; ni++) {
                int col = nW + ni * 8 + 2 * t;
                *(float2*)(my + m_loc * 256 + col) =
                    make_float2(acc[mi][ni][rr * 2 + 0], acc[mi][ni][rr * 2 + 1]);
            }
        }
    }
    __threadfence();
    __syncthreads();
    __shared__ int s_last;
    if (tid == 0) s_last = atomicAdd(&cnt[tl], 1);
    __syncthreads();
    if (s_last != 3) return;

    // last arriver: reduce 4 partials (fixed kq order -> deterministic) + epilogue
    const float* base = scr + (size_t)tl * 4 * TILE_ELEMS;
    for (int idx = tid; idx < TILE_ELEMS / 2; idx += 256) {
        int m_loc = idx >> 7, np = idx & 127;
        int col = np * 2;
        float2 v = make_float2(0.f, 0.f);
        #pragma unroll
        for (int k4 = 0; k4 < 4; k4++) {
            float2 p = __ldcg((const float2*)(base + (size_t)k4 * TILE_ELEMS
                                              + m_loc * 256 + col));
            v.x += p.x; v.y += p.y;
        }
        long long m = m0 + m_loc;
        float d = ds[(long long)b * NNODE + m];
        float2 sv = __half22float2(*(const __half2*)(selfb + m * 256 + col));
        if (EPI == 0) {
            float z0 = d * (v.x + sv.x);
            float z1 = d * (v.y + sv.y);
            int g16 = col >> 4, lp = (col >> 1) & 7;
            __half* Ch = (__half*)Cg + (size_t)b * NNODE * 256;
            *(__half2*)(Ch + m * 256 + (g16 << 4) + (pos8(lp) << 1)) =
                __floats2half2_rn(z0, z1);
        } else {
            float z0 = fmaf(d, v.x + sv.x, bias[col]);
            float z1 = fmaf(d, v.y + sv.y, bias[col + 1]);
            float* Cf = (float*)Cg + (size_t)b * NNODE * 256;
            *(float2*)(Cf + m * 256 + col) = make_float2(z0, z1);
        }
    }
    __syncthreads();
    if (tid == 0) cnt[tl] = 0;       // self-clean for next graph replay
}

// ===========================================================================
// NARROW feature GEMM (f32 acc): CTA 128x128, 4 warps, 2-stage, occ 3.
//   EPI 1: H = relu(acc+bias) -> half interleaved.
//   EPI 2: P2t[n][m] = ds[m]*acc (T+interleave) ; P2[m][n] plain.
// ===========================================================================
static constexpr int STAGE_BYTES = 32768;
static constexpr int SMEM_BYTES = 2 * STAGE_BYTES;     // 64 KB

template <int EPI>
__global__ void __launch_bounds__(128, 3) gemm_f16(
    const __half* __restrict__ Ag, const __half* __restrict__ Bg, void* __restrict__ Cg,
    const float* __restrict__ ds, const float* __restrict__ bias,
    __half* __restrict__ C2g,
    int K, long long lda, long long ldb, long long ldc) {

    extern __shared__ char smem[];
    const uint32_t sbase = smem_u32(smem);

    const int tid = threadIdx.x;
    const long long m0 = (long long)blockIdx.y * 128;
    const int n0 = blockIdx.x * 128;

    const __half* Ab = Ag;
    const __half* Bb = Bg;

    const int warp = tid >> 5, lane = tid & 31;
    const int gr = lane >> 2, t = lane & 3;
    const int mW = (warp >> 1) * 64, nW = (warp & 1) * 64;

    float acc[4][8][4];
    #pragma unroll
    for (int mi = 0; mi < 4; mi++)
        #pragma unroll
        for (int ni = 0; ni < 8; ni++)
            #pragma unroll
            for (int e = 0; e < 4; e++) acc[mi][ni][e] = 0.f;

    auto load_tile = [&](int st, int kt) {
        uint32_t sa = sbase + st * STAGE_BYTES;
        #pragma unroll
        for (int i = 0; i < 8; i++) {
            int cq = tid + i * 128;
            int r = cq >> 3, c = cq & 7;
            const __half* g = Ab + (m0 + r) * lda + kt + c * 8;
            cp_async16(sa + r * 128 + ((c ^ (r & 7)) << 4), g);
        }
        uint32_t sb = sa + 16384;
        #pragma unroll
        for (int i = 0; i < 8; i++) {
            int cq = tid + i * 128;
            int r = cq >> 3, c = cq & 7;
            const __half* g = Bb + (long long)(n0 + r) * ldb + kt + c * 8;
            cp_async16(sb + r * 128 + ((c ^ (r & 7)) << 4), g);
        }
    };

    const int nK = K / 64;
    load_tile(0, 0); cp_commit();

    for (int tt = 0; tt < nK; tt++) {
        if (tt + 1 < nK) { load_tile((tt + 1) & 1, (tt + 1) * 64); cp_commit(); cp_wait<1>(); }
        else cp_wait<0>();
        __syncthreads();

        uint32_t sa = sbase + (tt & 1) * STAGE_BYTES;
        uint32_t sb = sa + 16384;

        #pragma unroll
        for (int G = 0; G < 4; G++) {
            const int chunk = (G << 1) | (t >> 1);
            const uint32_t swo = ((chunk ^ gr) << 4) + ((t & 1) << 3);
            uint32_t a[4][4];
            #pragma unroll
            for (int mi = 0; mi < 4; mi++) {
                uint32_t ra = sa + (mW + mi * 16 + gr) * 128 + swo;
                lds64(a[mi][0], a[mi][2], ra);
                lds64(a[mi][1], a[mi][3], ra + 1024);
            }
            #pragma unroll
            for (int ni = 0; ni < 8; ni++) {
                uint32_t bf[2];
                lds64(bf[0], bf[1], sb + (nW + ni * 8 + gr) * 128 + swo);
                #pragma unroll
                for (int mi = 0; mi < 4; mi++)
                    mma_f16(acc[mi][ni], a[mi], bf);
            }
        }
        __syncthreads();
    }

    if (EPI == 2) {
        __half* sT = (__half*)smem;
        const long long gmb = (long long)blockIdx.y * 128;
        #pragma unroll
        for (int mi = 0; mi < 4; mi++) {
            #pragma unroll
            for (int rr = 0; rr < 2; rr++) {
                int m_loc = mW + mi * 16 + gr + rr * 8;
                long long gm = gmb + m_loc;
                float d = ds[gm];
                #pragma unroll
                for (int ni = 0; ni < 8; ni++) {
                    int n_loc = nW + ni * 8 + 2 * t;
                    float v0 = d * acc[mi][ni][rr * 2 + 0];
                    float v1 = d * acc[mi][ni][rr * 2 + 1];
                    __half2 hv = __floats2half2_rn(v0, v1);
                    *(__half2*)(sT + m_loc * 136 + n_loc) = hv;
                    *(__half2*)(C2g + gm * ldc + n0 + n_loc) = hv;   // P2 plain
                }
            }
        }
        __syncthreads();
        int bo = (int)(gmb >> 12);
        long long m0loc = gmb & 4095;
        __half* Ct = (__half*)Cg + (long long)bo * OUTC * NNODE
                   + (long long)(n0 + tid) * NNODE + m0loc;
        #pragma unroll
        for (int mg = 0; mg < 8; mg++) {
            __half2 ph[8];
            #pragma unroll
            for (int pp = 0; pp < 8; pp++) {
                int mA = mg * 16 + 2 * pp;
                ph[pos8(pp)] = __halves2half2(sT[mA * 136 + tid], sT[(mA + 1) * 136 + tid]);
            }
            uint4* dst = (uint4*)(Ct + mg * 16);
            dst[0] = *(uint4*)&ph[0];
            dst[1] = *(uint4*)&ph[4];
        }
        return;
    }

    // EPI == 1
    #pragma unroll
    for (int mi = 0; mi < 4; mi++) {
        #pragma unroll
        for (int rr = 0; rr < 2; rr++) {
            int m_loc = mW + mi * 16 + gr + rr * 8;
            long long m = m0 + m_loc;
            #pragma unroll
            for (int ni = 0; ni < 8; ni++) {
                int col = n0 + nW + ni * 8 + 2 * t;
                float v0 = fmaxf(acc[mi][ni][rr * 2 + 0] + bias[col], 0.f);
                float v1 = fmaxf(acc[mi][ni][rr * 2 + 1] + bias[col + 1], 0.f);
                int g16 = col >> 4, lp = (col >> 1) & 7;
                __half* Ch = (__half*)Cg;
                *(__half2*)(Ch + m * ldc + (g16 << 4) + (pos8(lp) << 1)) =
                    __floats2half2_rn(v0, v1);
            }
        }
    }
}

// ---------------------------------------------------------------------------
// launch
// ---------------------------------------------------------------------------
extern "C" void kernel_launch(void* const* d_in, const int* in_sizes, int n_in,
                              void* d_out, int out_size) {
    const float* x  = (const float*)d_in[0];
    const float* A  = (const float*)d_in[1];
    const float* W1 = (const float*)d_in[2];
    const float* b1 = (const float*)d_in[3];
    const float* W2 = (const float*)d_in[4];
    const float* b2 = (const float*)d_in[5];
    float* out = (float*)d_out;

    float *ds, *scr1, *scr2;
    int *cnt1, *cnt2;
    __half *Ar, *xs, *xst, *Z1, *H, *P2t, *P2, *W1t, *W2t;
    cudaGetSymbolAddress((void**)&ds,   g_ds);
    cudaGetSymbolAddress((void**)&Ar,   g_Ar);
    cudaGetSymbolAddress((void**)&xs,   g_xs);
    cudaGetSymbolAddress((void**)&xst,  g_xst);
    cudaGetSymbolAddress((void**)&Z1,   g_Z1);
    cudaGetSymbolAddress((void**)&H,    g_H);
    cudaGetSymbolAddress((void**)&P2t,  g_P2t);
    cudaGetSymbolAddress((void**)&P2,   g_P2);
    cudaGetSymbolAddress((void**)&W1t,  g_W1t);
    cudaGetSymbolAddress((void**)&W2t,  g_W2t);
    cudaGetSymbolAddress((void**)&scr1, g_scr1);
    cudaGetSymbolAddress((void**)&scr2, g_scr2);
    cudaGetSymbolAddress((void**)&cnt1, g_cnt1);
    cudaGetSymbolAddress((void**)&cnt2, g_cnt2);

    cudaFuncSetAttribute(gemm_agg<0>, cudaFuncAttributeMaxDynamicSharedMemorySize, WSMEM);
    cudaFuncSetAttribute(gemm_agg<3>, cudaFuncAttributeMaxDynamicSharedMemorySize, WSMEM);
    cudaFuncSetAttribute(gemm_f16<1>, cudaFuncAttributeMaxDynamicSharedMemorySize, SMEM_BYTES);
    cudaFuncSetAttribute(gemm_f16<2>, cudaFuncAttributeMaxDynamicSharedMemorySize, SMEM_BYTES);

    // prep
    prep_A_kernel<<<BATCH * NNODE, 256>>>(A, Ar, ds);
    prep_x_kernel<<<dim3(NNODE / 32, INC / 32, BATCH), 256>>>(x, ds, xs, xst);
    prep_W_kernel<<<(HIDC * (INC / 2) + 255) / 256, 256>>>(W1, W1t, INC, HIDC);
    prep_W_kernel<<<(OUTC * (HIDC / 2) + 255) / 256, 256>>>(W2, W2t, HIDC, OUTC);

    const int AGG_GRID = FULL_TILES + 4 * TAIL_TILES;   // 580

    // G1: Z1 = ds∘(A@xs + xs)
    gemm_agg<0><<<AGG_GRID, 256, WSMEM>>>(Ar, xst, Z1, xs, ds, nullptr, scr1, cnt1);

    // G2: H = relu(Z1@W1 + b1)
    gemm_f16<1><<<dim3(HIDC / 128, MT / 128, 1), 128, SMEM_BYTES>>>(
        Z1, W1t, H, ds, b1, nullptr, INC, INC, INC, HIDC);

    // G3: P2t = (ds∘(H@W2))^T + P2 plain copy
    gemm_f16<2><<<dim3(OUTC / 128, MT / 128, 1), 128, SMEM_BYTES>>>(
        H, W2t, P2t, ds, nullptr, P2, HIDC, HIDC, HIDC, OUTC);

    // G4: out = ds∘(A@P2 + P2) + b2
    gemm_agg<3><<<AGG_GRID, 256, WSMEM>>>(Ar, P2t, out, P2, ds, b2, scr2, cnt2);
}

// round 10
// speedup vs baseline: 1.1792x; 1.1611x over previous
#include <cuda_runtime.h>
#include <cuda_fp16.h>
#include <cstdint>

// ---------------------------------------------------------------------------
// GraphEncoder on GB300 (sm_103a) — fp16 mma.sync pipeline.
//
//   ds[i] = rsqrt(1 + rowsum(A)[i]);   xs = ds∘x  (fp16)
//   Z1  = ds∘(A@xs + xs)                     (agg, N=256)   [= nrm@x]
//   H   = relu(Z1@W1 + b1)                   (feature)
//   P2  = ds∘(H@W2)                          (feature)
//   out = ds∘(A@P2 + P2) + b2                (agg, N=256)
//
// R9: R6 wide agg kernel untouched, wave-quantization fixed by CLEAN 3-launch
// tail split-K: quarters(432 CTAs, K=1024 each, partials->scratch) -> full
// wave (148 CTAs, exact R6) -> reduce(108 CTAs, fixed-order sum + epilogue).
// No cold paths inside the hot kernel.
// ---------------------------------------------------------------------------

#define DEV_INLINE __device__ __forceinline__

static constexpr int BATCH = 8, NNODE = 4096, INC = 256, HIDC = 512, OUTC = 256;
static constexpr int MT = BATCH * NNODE;   // 32768

static constexpr int TILES      = 256;   // per agg: 8 batches x 32 m-tiles
static constexpr int FULL_TILES = 148;   // one exact wave of full-K CTAs
static constexpr int TAIL_TILES = TILES - FULL_TILES;   // 108
static constexpr int TILE_ELEMS = 128 * 256;            // fp32 per tile

// Scratch (allocation-free __device__ globals)
__device__ float  g_ds [MT];
__device__ __half g_Ar [(size_t)BATCH * NNODE * NNODE];          // 256 MB
__device__ __half g_xs [(size_t)MT * INC];                       // plain
__device__ __half g_xst[(size_t)BATCH * INC * NNODE];            // T, interleaved
__device__ __half g_Z1 [(size_t)MT * INC];                       // interleaved
__device__ __half g_H  [(size_t)MT * HIDC];                      // interleaved
__device__ __half g_P2t[(size_t)BATCH * OUTC * NNODE];           // T, interleaved
__device__ __half g_P2 [(size_t)MT * OUTC];                      // plain
__device__ __half g_W1t[HIDC * INC];
__device__ __half g_W2t[OUTC * HIDC];
__device__ float  g_scr[(size_t)TAIL_TILES * 4 * TILE_ELEMS];    // 56.6 MB

// ---------------------------------------------------------------------------
// helpers
// ---------------------------------------------------------------------------
DEV_INLINE int pos8(int p) { return ((p & 3) << 1) | ((p >> 2) & 1); }

DEV_INLINE void cp_async16(uint32_t saddr, const void* gmem) {
    asm volatile("cp.async.cg.shared.global [%0], [%1], 16;" :: "r"(saddr), "l"(gmem));
}
DEV_INLINE void cp_commit() { asm volatile("cp.async.commit_group;"); }
template <int N> DEV_INLINE void cp_wait() { asm volatile("cp.async.wait_group %0;" :: "n"(N)); }

DEV_INLINE uint32_t smem_u32(const void* p) {
    return (uint32_t)__cvta_generic_to_shared(p);
}

DEV_INLINE void lds64(uint32_t& x, uint32_t& y, uint32_t addr) {
    asm volatile("ld.shared.v2.b32 {%0, %1}, [%2];" : "=r"(x), "=r"(y) : "r"(addr));
}

DEV_INLINE void mma_f16(float* d, const uint32_t* a, const uint32_t* b) {
    asm volatile(
        "mma.sync.aligned.m16n8k16.row.col.f32.f16.f16.f32 "
        "{%0,%1,%2,%3},{%4,%5,%6,%7},{%8,%9},{%0,%1,%2,%3};"
        : "+f"(d[0]), "+f"(d[1]), "+f"(d[2]), "+f"(d[3])
        : "r"(a[0]), "r"(a[1]), "r"(a[2]), "r"(a[3]), "r"(b[0]), "r"(b[1]));
}

// ---------------------------------------------------------------------------
// prep_A: ds[row] = rsqrt(1+rowsum), Ar = fp16(A) pair-interleaved K-major
// ---------------------------------------------------------------------------
__global__ void __launch_bounds__(256) prep_A_kernel(const float* __restrict__ A,
                                                     __half* __restrict__ Ar,
                                                     float* __restrict__ ds) {
    __shared__ float srow[NNODE];
    long long row = blockIdx.x;
    const float4* p = (const float4*)(A + row * (long long)NNODE);
    float s = 0.f;
    #pragma unroll 2
    for (int i = threadIdx.x; i < NNODE / 4; i += 256) {
        float4 v = p[i];
        s += (v.x + v.y) + (v.z + v.w);
        *(float4*)(srow + 4 * i) = v;
    }
    #pragma unroll
    for (int o = 16; o; o >>= 1) s += __shfl_xor_sync(0xFFFFFFFFu, s, o);
    __shared__ float ws[8];
    if ((threadIdx.x & 31) == 0) ws[threadIdx.x >> 5] = s;
    __syncthreads();
    if (threadIdx.x == 0) {
        float tot = 0.f;
        #pragma unroll
        for (int i = 0; i < 8; i++) tot += ws[i];
        ds[row] = rsqrtf(tot + 1.0f);
    }
    int g = threadIdx.x;                  // 256 groups of 16 halfs
    const float* src = srow + 16 * g;
    __half2 ph[8];
    #pragma unroll
    for (int pp = 0; pp < 8; pp++)
        ph[pos8(pp)] = __floats2half2_rn(src[2 * pp], src[2 * pp + 1]);
    uint4* dst = (uint4*)(Ar + row * (long long)NNODE + 16 * g);
    dst[0] = *(uint4*)&ph[0];
    dst[1] = *(uint4*)&ph[4];
}

// ---------------------------------------------------------------------------
// prep_x: xs = fp16(ds∘x) plain row-major; xst = transposed, pair-interleaved
// ---------------------------------------------------------------------------
__global__ void __launch_bounds__(256) prep_x_kernel(const float* __restrict__ x,
                                                     const float* __restrict__ ds,
                                                     __half* __restrict__ xs,
                                                     __half* __restrict__ xst) {
    __shared__ __half sm[32][34];
    int m0 = blockIdx.x * 32, c0 = blockIdx.y * 32, b = blockIdx.z;
    #pragma unroll
    for (int r4 = 0; r4 < 4; r4++) {
        int idx = threadIdx.x + r4 * 256;
        int im = idx >> 5, ic = idx & 31;
        long long gm = (long long)b * NNODE + m0 + im;
        float v = x[gm * INC + c0 + ic] * ds[gm];
        __half h = __float2half_rn(v);
        sm[im][ic] = h;
        xs[gm * INC + c0 + ic] = h;
    }
    __syncthreads();
    #pragma unroll
    for (int r2 = 0; r2 < 2; r2++) {
        int pidx = threadIdx.x + r2 * 256;
        int jc = pidx >> 4, lp = pidx & 15;
        int grp = lp >> 3, pp = lp & 7;
        int mA = grp * 16 + 2 * pp;
        __half2 hv = __halves2half2(sm[mA][jc], sm[mA + 1][jc]);
        long long dst = (long long)b * INC * NNODE + (long long)(c0 + jc) * NNODE
                      + m0 + grp * 16 + pos8(pp) * 2;
        *(__half2*)(xst + dst) = hv;
    }
}

// ---------------------------------------------------------------------------
// prep_W: Wt[n][k-interleaved] = fp16(W[k][n])
// ---------------------------------------------------------------------------
__global__ void __launch_bounds__(256) prep_W_kernel(const float* __restrict__ W,
                                                     __half* __restrict__ Wt,
                                                     int K, int N) {
    int id = blockIdx.x * 256 + threadIdx.x;
    if (id >= N * (K / 2)) return;
    int n = id / (K / 2), pk = id % (K / 2);
    int grp = pk >> 3, pp = pk & 7;
    int k = 2 * pk;
    __half2 hv = __floats2half2_rn(W[(long long)k * N + n], W[(long long)(k + 1) * N + n]);
    *(__half2*)(Wt + (long long)n * K + grp * 16 + pos8(pp) * 2) = hv;
}

// ===========================================================================
// Shared agg mainloop (CTA 128x256, 8 warps of 64x64, BK=64, 4-stage ring).
// Accumulates into acc[4][8][4]. No cold paths.
// ===========================================================================
static constexpr int WSTAGE = 49152;                 // A 16KB + B 32KB
static constexpr int WSMEM  = 4 * WSTAGE;            // 192 KB

struct AggCtx {
    const __half* Ab; const __half* Bb;
    int m0; int warp, lane, gr, t, mW, nW;
};

DEV_INLINE void agg_mainloop(const AggCtx& cx, uint32_t sbase, int tid,
                             int k0, int iters, float acc[4][8][4]) {
    auto load_tile = [&](int st, int kt) {
        uint32_t sa = sbase + st * WSTAGE;
        #pragma unroll
        for (int i = 0; i < 4; i++) {
            int cq = tid + i * 256;
            int r = cq >> 3, c = cq & 7;
            const __half* g = cx.Ab + (size_t)(cx.m0 + r) * NNODE + kt + c * 8;
            cp_async16(sa + r * 128 + ((c ^ (r & 7)) << 4), g);
        }
        uint32_t sb = sa + 16384;
        #pragma unroll
        for (int i = 0; i < 8; i++) {
            int cq = tid + i * 256;
            int r = cq >> 3, c = cq & 7;
            const __half* g = cx.Bb + (size_t)r * NNODE + kt + c * 8;
            cp_async16(sb + r * 128 + ((c ^ (r & 7)) << 4), g);
        }
    };

    load_tile(0, k0); cp_commit();
    load_tile(1, k0 + 64); cp_commit();
    load_tile(2, k0 + 128); cp_commit();

    for (int tt = 0; tt < iters; tt++) {
        int rem = iters - 1 - tt;
        if (rem >= 2) cp_wait<2>(); else if (rem == 1) cp_wait<1>(); else cp_wait<0>();
        __syncthreads();
        if (tt + 3 < iters) { load_tile((tt + 3) & 3, k0 + (tt + 3) * 64); cp_commit(); }

        uint32_t sa = sbase + (tt & 3) * WSTAGE;
        uint32_t sb = sa + 16384;

        #pragma unroll
        for (int G = 0; G < 4; G++) {
            const int chunk = (G << 1) | (cx.t >> 1);
            const uint32_t swo = ((chunk ^ cx.gr) << 4) + ((cx.t & 1) << 3);
            uint32_t a[4][4];
            #pragma unroll
            for (int mi = 0; mi < 4; mi++) {
                uint32_t ra = sa + (cx.mW + mi * 16 + cx.gr) * 128 + swo;
                lds64(a[mi][0], a[mi][2], ra);
                lds64(a[mi][1], a[mi][3], ra + 1024);
            }
            #pragma unroll
            for (int ni = 0; ni < 8; ni++) {
                uint32_t bf[2];
                lds64(bf[0], bf[1], sb + (cx.nW + ni * 8 + cx.gr) * 128 + swo);
                #pragma unroll
                for (int mi = 0; mi < 4; mi++)
                    mma_f16(acc[mi][ni], a[mi], bf);
            }
        }
    }
    __syncthreads();
}

DEV_INLINE AggCtx make_ctx(const __half* Ag, const __half* Bg, int tile, int tid) {
    AggCtx cx;
    int b = tile >> 5;
    cx.m0 = (tile & 31) * 128;
    cx.Ab = Ag + (size_t)b * NNODE * NNODE;
    cx.Bb = Bg + (size_t)b * 256 * NNODE;
    cx.warp = tid >> 5; cx.lane = tid & 31;
    cx.gr = cx.lane >> 2; cx.t = cx.lane & 3;
    cx.mW = (cx.warp >> 2) * 64; cx.nW = (cx.warp & 3) * 64;
    return cx;
}

// ---- full-K kernel: tiles 0..147, normal GCN epilogue ----
template <int EPI>
__global__ void __launch_bounds__(256, 1) gemm_agg_full(
    const __half* __restrict__ Ag, const __half* __restrict__ Bg, void* __restrict__ Cg,
    const __half* __restrict__ selfg, const float* __restrict__ ds,
    const float* __restrict__ bias) {

    extern __shared__ char smem[];
    const uint32_t sbase = smem_u32(smem);
    const int tid = threadIdx.x;
    const int tile = blockIdx.x;
    const int b = tile >> 5;
    AggCtx cx = make_ctx(Ag, Bg, tile, tid);

    float acc[4][8][4];
    #pragma unroll
    for (int mi = 0; mi < 4; mi++)
        #pragma unroll
        for (int ni = 0; ni < 8; ni++)
            #pragma unroll
            for (int e = 0; e < 4; e++) acc[mi][ni][e] = 0.f;

    agg_mainloop(cx, sbase, tid, 0, 64, acc);

    const __half* selfb = selfg + (size_t)b * NNODE * 256;
    #pragma unroll
    for (int mi = 0; mi < 4; mi++) {
        #pragma unroll
        for (int rr = 0; rr < 2; rr++) {
            int m_loc = cx.mW + mi * 16 + cx.gr + rr * 8;
            long long m = cx.m0 + m_loc;
            float d = ds[(long long)b * NNODE + m];
            #pragma unroll
            for (int ni = 0; ni < 8; ni++) {
                int col = cx.nW + ni * 8 + 2 * cx.t;
                float v0 = acc[mi][ni][rr * 2 + 0];
                float v1 = acc[mi][ni][rr * 2 + 1];
                float2 sv = __half22float2(*(const __half2*)(selfb + m * 256 + col));
                if (EPI == 0) {
                    v0 = d * (v0 + sv.x);
                    v1 = d * (v1 + sv.y);
                    int g16 = col >> 4, lp = (col >> 1) & 7;
                    __half* Ch = (__half*)Cg + (size_t)b * NNODE * 256;
                    *(__half2*)(Ch + m * 256 + (g16 << 4) + (pos8(lp) << 1)) =
                        __floats2half2_rn(v0, v1);
                } else {
                    v0 = fmaf(d, v0 + sv.x, bias[col]);
                    v1 = fmaf(d, v1 + sv.y, bias[col + 1]);
                    float* Cf = (float*)Cg + (size_t)b * NNODE * 256;
                    *(float2*)(Cf + m * 256 + col) = make_float2(v0, v1);
                }
            }
        }
    }
}

// ---- quarter-K kernel: tiles 148..255, partial fp32 -> scratch ----
__global__ void __launch_bounds__(256, 1) gemm_agg_part(
    const __half* __restrict__ Ag, const __half* __restrict__ Bg,
    float* __restrict__ scr) {

    extern __shared__ char smem[];
    const uint32_t sbase = smem_u32(smem);
    const int tid = threadIdx.x;
    const int q = blockIdx.x;
    const int tile = FULL_TILES + (q >> 2);
    const int kq = q & 3;
    AggCtx cx = make_ctx(Ag, Bg, tile, tid);

    float acc[4][8][4];
    #pragma unroll
    for (int mi = 0; mi < 4; mi++)
        #pragma unroll
        for (int ni = 0; ni < 8; ni++)
            #pragma unroll
            for (int e = 0; e < 4; e++) acc[mi][ni][e] = 0.f;

    agg_mainloop(cx, sbase, tid, kq * 1024, 16, acc);

    float* my = scr + ((size_t)(tile - FULL_TILES) * 4 + kq) * TILE_ELEMS;
    #pragma unroll
    for (int mi = 0; mi < 4; mi++) {
        #pragma unroll
        for (int rr = 0; rr < 2; rr++) {
            int m_loc = cx.mW + mi * 16 + cx.gr + rr * 8;
            #pragma unroll
            for (int ni = 0; ni < 8; ni++) {
                int col = cx.nW + ni * 8 + 2 * cx.t;
                *(float2*)(my + m_loc * 256 + col) =
                    make_float2(acc[mi][ni][rr * 2 + 0], acc[mi][ni][rr * 2 + 1]);
            }
        }
    }
}

// ---- reduce kernel: fixed-order sum of 4 partials + GCN epilogue ----
template <int EPI>
__global__ void __launch_bounds__(256) agg_reduce(
    const float* __restrict__ scr, void* __restrict__ Cg,
    const __half* __restrict__ selfg, const float* __restrict__ ds,
    const float* __restrict__ bias) {

    const int tl = blockIdx.x;
    const int tile = FULL_TILES + tl;
    const int b = tile >> 5;
    const int m0 = (tile & 31) * 128;
    const __half* selfb = selfg + (size_t)b * NNODE * 256;
    const float* base = scr + (size_t)tl * 4 * TILE_ELEMS;

    for (int idx = threadIdx.x; idx < TILE_ELEMS / 2; idx += 256) {
        int m_loc = idx >> 7;
        int col = (idx & 127) * 2;
        float2 v = make_float2(0.f, 0.f);
        #pragma unroll
        for (int k4 = 0; k4 < 4; k4++) {
            float2 p = __ldcg((const float2*)(base + (size_t)k4 * TILE_ELEMS
                                              + m_loc * 256 + col));
            v.x += p.x; v.y += p.y;
        }
        long long m = m0 + m_loc;
        float d = ds[(long long)b * NNODE + m];
        float2 sv = __half22float2(*(const __half2*)(selfb + m * 256 + col));
        if (EPI == 0) {
            float z0 = d * (v.x + sv.x);
            float z1 = d * (v.y + sv.y);
            int g16 = col >> 4, lp = (col >> 1) & 7;
            __half* Ch = (__half*)Cg + (size_t)b * NNODE * 256;
            *(__half2*)(Ch + m * 256 + (g16 << 4) + (pos8(lp) << 1)) =
                __floats2half2_rn(z0, z1);
        } else {
            float z0 = fmaf(d, v.x + sv.x, bias[col]);
            float z1 = fmaf(d, v.y + sv.y, bias[col + 1]);
            float* Cf = (float*)Cg + (size_t)b * NNODE * 256;
            *(float2*)(Cf + m * 256 + col) = make_float2(z0, z1);
        }
    }
}

// ===========================================================================
// NARROW feature GEMM (f32 acc): CTA 128x128, 4 warps, 2-stage, occ 3.
//   EPI 1: H = relu(acc+bias) -> half interleaved.
//   EPI 2: P2t[n][m] = ds[m]*acc (T+interleave) ; P2[m][n] plain.
// ===========================================================================
static constexpr int STAGE_BYTES = 32768;
static constexpr int SMEM_BYTES = 2 * STAGE_BYTES;     // 64 KB

template <int EPI>
__global__ void __launch_bounds__(128, 3) gemm_f16(
    const __half* __restrict__ Ag, const __half* __restrict__ Bg, void* __restrict__ Cg,
    const float* __restrict__ ds, const float* __restrict__ bias,
    __half* __restrict__ C2g,
    int K, long long lda, long long ldb, long long ldc) {

    extern __shared__ char smem[];
    const uint32_t sbase = smem_u32(smem);

    const int tid = threadIdx.x;
    const long long m0 = (long long)blockIdx.y * 128;
    const int n0 = blockIdx.x * 128;

    const __half* Ab = Ag;
    const __half* Bb = Bg;

    const int warp = tid >> 5, lane = tid & 31;
    const int gr = lane >> 2, t = lane & 3;
    const int mW = (warp >> 1) * 64, nW = (warp & 1) * 64;

    float acc[4][8][4];
    #pragma unroll
    for (int mi = 0; mi < 4; mi++)
        #pragma unroll
        for (int ni = 0; ni < 8; ni++)
            #pragma unroll
            for (int e = 0; e < 4; e++) acc[mi][ni][e] = 0.f;

    auto load_tile = [&](int st, int kt) {
        uint32_t sa = sbase + st * STAGE_BYTES;
        #pragma unroll
        for (int i = 0; i < 8; i++) {
            int cq = tid + i * 128;
            int r = cq >> 3, c = cq & 7;
            const __half* g = Ab + (m0 + r) * lda + kt + c * 8;
            cp_async16(sa + r * 128 + ((c ^ (r & 7)) << 4), g);
        }
        uint32_t sb = sa + 16384;
        #pragma unroll
        for (int i = 0; i < 8; i++) {
            int cq = tid + i * 128;
            int r = cq >> 3, c = cq & 7;
            const __half* g = Bb + (long long)(n0 + r) * ldb + kt + c * 8;
            cp_async16(sb + r * 128 + ((c ^ (r & 7)) << 4), g);
        }
    };

    const int nK = K / 64;
    load_tile(0, 0); cp_commit();

    for (int tt = 0; tt < nK; tt++) {
        if (tt + 1 < nK) { load_tile((tt + 1) & 1, (tt + 1) * 64); cp_commit(); cp_wait<1>(); }
        else cp_wait<0>();
        __syncthreads();

        uint32_t sa = sbase + (tt & 1) * STAGE_BYTES;
        uint32_t sb = sa + 16384;

        #pragma unroll
        for (int G = 0; G < 4; G++) {
            const int chunk = (G << 1) | (t >> 1);
            const uint32_t swo = ((chunk ^ gr) << 4) + ((t & 1) << 3);
            uint32_t a[4][4];
            #pragma unroll
            for (int mi = 0; mi < 4; mi++) {
                uint32_t ra = sa + (mW + mi * 16 + gr) * 128 + swo;
                lds64(a[mi][0], a[mi][2], ra);
                lds64(a[mi][1], a[mi][3], ra + 1024);
            }
            #pragma unroll
            for (int ni = 0; ni < 8; ni++) {
                uint32_t bf[2];
                lds64(bf[0], bf[1], sb + (nW + ni * 8 + gr) * 128 + swo);
                #pragma unroll
                for (int mi = 0; mi < 4; mi++)
                    mma_f16(acc[mi][ni], a[mi], bf);
            }
        }
        __syncthreads();
    }

    if (EPI == 2) {
        __half* sT = (__half*)smem;
        const long long gmb = (long long)blockIdx.y * 128;
        #pragma unroll
        for (int mi = 0; mi < 4; mi++) {
            #pragma unroll
            for (int rr = 0; rr < 2; rr++) {
                int m_loc = mW + mi * 16 + gr + rr * 8;
                long long gm = gmb + m_loc;
                float d = ds[gm];
                #pragma unroll
                for (int ni = 0; ni < 8; ni++) {
                    int n_loc = nW + ni * 8 + 2 * t;
                    float v0 = d * acc[mi][ni][rr * 2 + 0];
                    float v1 = d * acc[mi][ni][rr * 2 + 1];
                    __half2 hv = __floats2half2_rn(v0, v1);
                    *(__half2*)(sT + m_loc * 136 + n_loc) = hv;
                    *(__half2*)(C2g + gm * ldc + n0 + n_loc) = hv;   // P2 plain
                }
            }
        }
        __syncthreads();
        int bo = (int)(gmb >> 12);
        long long m0loc = gmb & 4095;
        __half* Ct = (__half*)Cg + (long long)bo * OUTC * NNODE
                   + (long long)(n0 + tid) * NNODE + m0loc;
        #pragma unroll
        for (int mg = 0; mg < 8; mg++) {
            __half2 ph[8];
            #pragma unroll
            for (int pp = 0; pp < 8; pp++) {
                int mA = mg * 16 + 2 * pp;
                ph[pos8(pp)] = __halves2half2(sT[mA * 136 + tid], sT[(mA + 1) * 136 + tid]);
            }
            uint4* dst = (uint4*)(Ct + mg * 16);
            dst[0] = *(uint4*)&ph[0];
            dst[1] = *(uint4*)&ph[4];
        }
        return;
    }

    // EPI == 1
    #pragma unroll
    for (int mi = 0; mi < 4; mi++) {
        #pragma unroll
        for (int rr = 0; rr < 2; rr++) {
            int m_loc = mW + mi * 16 + gr + rr * 8;
            long long m = m0 + m_loc;
            #pragma unroll
            for (int ni = 0; ni < 8; ni++) {
                int col = n0 + nW + ni * 8 + 2 * t;
                float v0 = fmaxf(acc[mi][ni][rr * 2 + 0] + bias[col], 0.f);
                float v1 = fmaxf(acc[mi][ni][rr * 2 + 1] + bias[col + 1], 0.f);
                int g16 = col >> 4, lp = (col >> 1) & 7;
                __half* Ch = (__half*)Cg;
                *(__half2*)(Ch + m * ldc + (g16 << 4) + (pos8(lp) << 1)) =
                    __floats2half2_rn(v0, v1);
            }
        }
    }
}

// ---------------------------------------------------------------------------
// launch
// ---------------------------------------------------------------------------
extern "C" void kernel_launch(void* const* d_in, const int* in_sizes, int n_in,
                              void* d_out, int out_size) {
    const float* x  = (const float*)d_in[0];
    const float* A  = (const float*)d_in[1];
    const float* W1 = (const float*)d_in[2];
    const float* b1 = (const float*)d_in[3];
    const float* W2 = (const float*)d_in[4];
    const float* b2 = (const float*)d_in[5];
    float* out = (float*)d_out;

    float *ds, *scr;
    __half *Ar, *xs, *xst, *Z1, *H, *P2t, *P2, *W1t, *W2t;
    cudaGetSymbolAddress((void**)&ds,  g_ds);
    cudaGetSymbolAddress((void**)&Ar,  g_Ar);
    cudaGetSymbolAddress((void**)&xs,  g_xs);
    cudaGetSymbolAddress((void**)&xst, g_xst);
    cudaGetSymbolAddress((void**)&Z1,  g_Z1);
    cudaGetSymbolAddress((void**)&H,   g_H);
    cudaGetSymbolAddress((void**)&P2t, g_P2t);
    cudaGetSymbolAddress((void**)&P2,  g_P2);
    cudaGetSymbolAddress((void**)&W1t, g_W1t);
    cudaGetSymbolAddress((void**)&W2t, g_W2t);
    cudaGetSymbolAddress((void**)&scr, g_scr);

    cudaFuncSetAttribute(gemm_agg_full<0>, cudaFuncAttributeMaxDynamicSharedMemorySize, WSMEM);
    cudaFuncSetAttribute(gemm_agg_full<3>, cudaFuncAttributeMaxDynamicSharedMemorySize, WSMEM);
    cudaFuncSetAttribute(gemm_agg_part,    cudaFuncAttributeMaxDynamicSharedMemorySize, WSMEM);
    cudaFuncSetAttribute(gemm_f16<1>, cudaFuncAttributeMaxDynamicSharedMemorySize, SMEM_BYTES);
    cudaFuncSetAttribute(gemm_f16<2>, cudaFuncAttributeMaxDynamicSharedMemorySize, SMEM_BYTES);

    // prep
    prep_A_kernel<<<BATCH * NNODE, 256>>>(A, Ar, ds);
    prep_x_kernel<<<dim3(NNODE / 32, INC / 32, BATCH), 256>>>(x, ds, xs, xst);
    prep_W_kernel<<<(HIDC * (INC / 2) + 255) / 256, 256>>>(W1, W1t, INC, HIDC);
    prep_W_kernel<<<(OUTC * (HIDC / 2) + 255) / 256, 256>>>(W2, W2t, HIDC, OUTC);

    // G1: Z1 = ds∘(A@xs + xs)  — quarters, full wave, reduce
    gemm_agg_part<<<4 * TAIL_TILES, 256, WSMEM>>>(Ar, xst, scr);
    gemm_agg_full<0><<<FULL_TILES, 256, WSMEM>>>(Ar, xst, Z1, xs, ds, nullptr);
    agg_reduce<0><<<TAIL_TILES, 256>>>(scr, Z1, xs, ds, nullptr);

    // G2: H = relu(Z1@W1 + b1)
    gemm_f16<1><<<dim3(HIDC / 128, MT / 128, 1), 128, SMEM_BYTES>>>(
        Z1, W1t, H, ds, b1, nullptr, INC, INC, INC, HIDC);

    // G3: P2t = (ds∘(H@W2))^T + P2 plain copy
    gemm_f16<2><<<dim3(OUTC / 128, MT / 128, 1), 128, SMEM_BYTES>>>(
        H, W2t, P2t, ds, nullptr, P2, HIDC, HIDC, HIDC, OUTC);

    // G4: out = ds∘(A@P2 + P2) + b2  — quarters, full wave, reduce
    gemm_agg_part<<<4 * TAIL_TILES, 256, WSMEM>>>(Ar, P2t, scr);
    gemm_agg_full<3><<<FULL_TILES, 256, WSMEM>>>(Ar, P2t, out, P2, ds, b2);
    agg_reduce<3><<<TAIL_TILES, 256>>>(scr, out, P2, ds, b2);
}

// round 11
// speedup vs baseline: 1.2557x; 1.0648x over previous
#include <cuda_runtime.h>
#include <cuda_fp16.h>
#include <cstdint>

// ---------------------------------------------------------------------------
// GraphEncoder on GB300 (sm_103a) — fp16 mma.sync pipeline.
//
//   ds[i] = rsqrt(1 + rowsum(A)[i]);   xs = ds∘x  (fp16)
//   Z1  = ds∘(A@xs + xs)                     (agg, N=256)   [= nrm@x]
//   H   = relu(Z1@W1 + b1)                   (feature — smem only, fused)
//   P2  = ds∘(H@W2)                          (feature — fused kernel)
//   out = ds∘(A@P2 + P2) + b2                (agg, N=256)
//
// R10: exact R6 agg kernels (best known); G2+G3 fused into one kernel that
// keeps H entirely in shared memory (128KB operand-layout stages); prep_W
// launches merged. 6 launches total.
// ---------------------------------------------------------------------------

#define DEV_INLINE __device__ __forceinline__

static constexpr int BATCH = 8, NNODE = 4096, INC = 256, HIDC = 512, OUTC = 256;
static constexpr int MT = BATCH * NNODE;   // 32768

// Scratch (allocation-free __device__ globals)
__device__ float  g_ds [MT];
__device__ __half g_Ar [(size_t)BATCH * NNODE * NNODE];          // 256 MB
__device__ __half g_xs [(size_t)MT * INC];                       // plain
__device__ __half g_xst[(size_t)BATCH * INC * NNODE];            // T, interleaved
__device__ __half g_Z1 [(size_t)MT * INC];                       // interleaved
__device__ __half g_P2t[(size_t)BATCH * OUTC * NNODE];           // T, interleaved
__device__ __half g_P2 [(size_t)MT * OUTC];                      // plain
__device__ __half g_W1t[HIDC * INC];                             // interleaved K-major
__device__ __half g_W2t[OUTC * HIDC];                            // interleaved K-major

// ---------------------------------------------------------------------------
// helpers
// ---------------------------------------------------------------------------
DEV_INLINE int pos8(int p) { return ((p & 3) << 1) | ((p >> 2) & 1); }

DEV_INLINE void cp_async16(uint32_t saddr, const void* gmem) {
    asm volatile("cp.async.cg.shared.global [%0], [%1], 16;" :: "r"(saddr), "l"(gmem));
}
DEV_INLINE void cp_commit() { asm volatile("cp.async.commit_group;"); }
template <int N> DEV_INLINE void cp_wait() { asm volatile("cp.async.wait_group %0;" :: "n"(N)); }

DEV_INLINE uint32_t smem_u32(const void* p) {
    return (uint32_t)__cvta_generic_to_shared(p);
}

DEV_INLINE void lds64(uint32_t& x, uint32_t& y, uint32_t addr) {
    asm volatile("ld.shared.v2.b32 {%0, %1}, [%2];" : "=r"(x), "=r"(y) : "r"(addr));
}

DEV_INLINE void mma_f16(float* d, const uint32_t* a, const uint32_t* b) {
    asm volatile(
        "mma.sync.aligned.m16n8k16.row.col.f32.f16.f16.f32 "
        "{%0,%1,%2,%3},{%4,%5,%6,%7},{%8,%9},{%0,%1,%2,%3};"
        : "+f"(d[0]), "+f"(d[1]), "+f"(d[2]), "+f"(d[3])
        : "r"(a[0]), "r"(a[1]), "r"(a[2]), "r"(a[3]), "r"(b[0]), "r"(b[1]));
}

// ---------------------------------------------------------------------------
// prep_A: ds[row] = rsqrt(1+rowsum), Ar = fp16(A) pair-interleaved K-major
// ---------------------------------------------------------------------------
__global__ void __launch_bounds__(256) prep_A_kernel(const float* __restrict__ A,
                                                     __half* __restrict__ Ar,
                                                     float* __restrict__ ds) {
    __shared__ float srow[NNODE];
    long long row = blockIdx.x;
    const float4* p = (const float4*)(A + row * (long long)NNODE);
    float s = 0.f;
    #pragma unroll 2
    for (int i = threadIdx.x; i < NNODE / 4; i += 256) {
        float4 v = p[i];
        s += (v.x + v.y) + (v.z + v.w);
        *(float4*)(srow + 4 * i) = v;
    }
    #pragma unroll
    for (int o = 16; o; o >>= 1) s += __shfl_xor_sync(0xFFFFFFFFu, s, o);
    __shared__ float ws[8];
    if ((threadIdx.x & 31) == 0) ws[threadIdx.x >> 5] = s;
    __syncthreads();
    if (threadIdx.x == 0) {
        float tot = 0.f;
        #pragma unroll
        for (int i = 0; i < 8; i++) tot += ws[i];
        ds[row] = rsqrtf(tot + 1.0f);
    }
    int g = threadIdx.x;                  // 256 groups of 16 halfs
    const float* src = srow + 16 * g;
    __half2 ph[8];
    #pragma unroll
    for (int pp = 0; pp < 8; pp++)
        ph[pos8(pp)] = __floats2half2_rn(src[2 * pp], src[2 * pp + 1]);
    uint4* dst = (uint4*)(Ar + row * (long long)NNODE + 16 * g);
    dst[0] = *(uint4*)&ph[0];
    dst[1] = *(uint4*)&ph[4];
}

// ---------------------------------------------------------------------------
// prep_x: xs = fp16(ds∘x) plain row-major; xst = transposed, pair-interleaved
// ---------------------------------------------------------------------------
__global__ void __launch_bounds__(256) prep_x_kernel(const float* __restrict__ x,
                                                     const float* __restrict__ ds,
                                                     __half* __restrict__ xs,
                                                     __half* __restrict__ xst) {
    __shared__ __half sm[32][34];
    int m0 = blockIdx.x * 32, c0 = blockIdx.y * 32, b = blockIdx.z;
    #pragma unroll
    for (int r4 = 0; r4 < 4; r4++) {
        int idx = threadIdx.x + r4 * 256;
        int im = idx >> 5, ic = idx & 31;
        long long gm = (long long)b * NNODE + m0 + im;
        float v = x[gm * INC + c0 + ic] * ds[gm];
        __half h = __float2half_rn(v);
        sm[im][ic] = h;
        xs[gm * INC + c0 + ic] = h;
    }
    __syncthreads();
    #pragma unroll
    for (int r2 = 0; r2 < 2; r2++) {
        int pidx = threadIdx.x + r2 * 256;
        int jc = pidx >> 4, lp = pidx & 15;
        int grp = lp >> 3, pp = lp & 7;
        int mA = grp * 16 + 2 * pp;
        __half2 hv = __halves2half2(sm[mA][jc], sm[mA + 1][jc]);
        long long dst = (long long)b * INC * NNODE + (long long)(c0 + jc) * NNODE
                      + m0 + grp * 16 + pos8(pp) * 2;
        *(__half2*)(xst + dst) = hv;
    }
}

// ---------------------------------------------------------------------------
// prep_W_both: one launch for both weight transposes.
//   blocks [0,256)  : W1t[h][k-intlv] = fp16(W1[k][h])   (K=256, N=512)
//   blocks [256,512): W2t[o][k-intlv] = fp16(W2[k][o])   (K=512, N=256)
// ---------------------------------------------------------------------------
__global__ void __launch_bounds__(256) prep_W_both(const float* __restrict__ W1,
                                                   const float* __restrict__ W2,
                                                   __half* __restrict__ W1t,
                                                   __half* __restrict__ W2t) {
    int blk = blockIdx.x;
    const float* W; __half* Wt; int K, N, id;
    if (blk < 256) { W = W1; Wt = W1t; K = INC;  N = HIDC; id = blk * 256 + threadIdx.x; }
    else           { W = W2; Wt = W2t; K = HIDC; N = OUTC; id = (blk - 256) * 256 + threadIdx.x; }
    if (id >= N * (K / 2)) return;
    int n = id / (K / 2), pk = id % (K / 2);
    int grp = pk >> 3, pp = pk & 7;
    int k = 2 * pk;
    __half2 hv = __floats2half2_rn(W[(long long)k * N + n], W[(long long)(k + 1) * N + n]);
    *(__half2*)(Wt + (long long)n * K + grp * 16 + pos8(pp) * 2) = hv;
}

// ===========================================================================
// WIDE agg GEMM (exact R6): C = A(MxK) @ B(NxK)^T, CTA 128x256, 8 warps of
// 64x64, BK=64, 4-stage ring (192KB), occ 1.
//   EPI 0: Z1[m][n] = ds[m]*(acc + self[m][n])      -> half interleaved
//   EPI 3: out[m][n] = ds[m]*(acc + self[m][n]) + bias[n]  -> fp32
// ===========================================================================
static constexpr int WSTAGE = 49152;                 // A 16KB + B 32KB
static constexpr int WSMEM  = 4 * WSTAGE;            // 192 KB

template <int EPI>
__global__ void __launch_bounds__(256, 1) gemm_f16_wide(
    const __half* __restrict__ Ag, const __half* __restrict__ Bg, void* __restrict__ Cg,
    const __half* __restrict__ selfg, const float* __restrict__ ds,
    const float* __restrict__ bias,
    int K, long long lda, long long ldb, long long ldc, long long ldself,
    long long sAb, long long sBb, long long sCb, long long sSelfb) {

    extern __shared__ char smem[];
    const uint32_t sbase = smem_u32(smem);

    const int tid = threadIdx.x;
    const int b = blockIdx.z;
    const long long m0 = (long long)blockIdx.y * 128;
    const int n0 = blockIdx.x * 256;

    const __half* Ab = Ag + (long long)b * sAb;
    const __half* Bb = Bg + (long long)b * sBb;

    const int warp = tid >> 5, lane = tid & 31;
    const int gr = lane >> 2, t = lane & 3;
    const int mW = (warp >> 2) * 64, nW = (warp & 3) * 64;

    float acc[4][8][4];
    #pragma unroll
    for (int mi = 0; mi < 4; mi++)
        #pragma unroll
        for (int ni = 0; ni < 8; ni++)
            #pragma unroll
            for (int e = 0; e < 4; e++) acc[mi][ni][e] = 0.f;

    auto load_tile = [&](int st, int kt) {
        uint32_t sa = sbase + st * WSTAGE;
        #pragma unroll
        for (int i = 0; i < 4; i++) {                       // A: 1024 chunks
            int cq = tid + i * 256;
            int r = cq >> 3, c = cq & 7;
            const __half* g = Ab + (m0 + r) * lda + kt + c * 8;
            cp_async16(sa + r * 128 + ((c ^ (r & 7)) << 4), g);
        }
        uint32_t sb = sa + 16384;
        #pragma unroll
        for (int i = 0; i < 8; i++) {                       // B: 2048 chunks
            int cq = tid + i * 256;
            int r = cq >> 3, c = cq & 7;
            const __half* g = Bb + (long long)(n0 + r) * ldb + kt + c * 8;
            cp_async16(sb + r * 128 + ((c ^ (r & 7)) << 4), g);
        }
    };

    const int nK = K / 64;                                  // 64 for agg
    load_tile(0, 0); cp_commit();
    load_tile(1, 64); cp_commit();
    load_tile(2, 128); cp_commit();

    for (int tt = 0; tt < nK; tt++) {
        int rem = nK - 1 - tt;
        if (rem >= 2) cp_wait<2>(); else if (rem == 1) cp_wait<1>(); else cp_wait<0>();
        __syncthreads();
        if (tt + 3 < nK) { load_tile((tt + 3) & 3, (tt + 3) * 64); cp_commit(); }

        uint32_t sa = sbase + (tt & 3) * WSTAGE;
        uint32_t sb = sa + 16384;

        #pragma unroll
        for (int G = 0; G < 4; G++) {
            const int chunk = (G << 1) | (t >> 1);
            const uint32_t swo = ((chunk ^ gr) << 4) + ((t & 1) << 3);
            uint32_t a[4][4];
            #pragma unroll
            for (int mi = 0; mi < 4; mi++) {
                uint32_t ra = sa + (mW + mi * 16 + gr) * 128 + swo;
                lds64(a[mi][0], a[mi][2], ra);
                lds64(a[mi][1], a[mi][3], ra + 1024);
            }
            #pragma unroll
            for (int ni = 0; ni < 8; ni++) {
                uint32_t bf[2];
                lds64(bf[0], bf[1], sb + (nW + ni * 8 + gr) * 128 + swo);
                #pragma unroll
                for (int mi = 0; mi < 4; mi++)
                    mma_f16(acc[mi][ni], a[mi], bf);
            }
        }
    }
    __syncthreads();

    // ---------------- epilogue ----------------
    const __half* selfb = selfg + (long long)b * sSelfb;
    #pragma unroll
    for (int mi = 0; mi < 4; mi++) {
        #pragma unroll
        for (int rr = 0; rr < 2; rr++) {
            int m_loc = mW + mi * 16 + gr + rr * 8;
            long long m = m0 + m_loc;
            float d = ds[(long long)b * NNODE + m];
            #pragma unroll
            for (int ni = 0; ni < 8; ni++) {
                int col = n0 + nW + ni * 8 + 2 * t;
                float v0 = acc[mi][ni][rr * 2 + 0];
                float v1 = acc[mi][ni][rr * 2 + 1];
                float2 sv = __half22float2(*(const __half2*)(selfb + m * ldself + col));
                if (EPI == 0) {
                    v0 = d * (v0 + sv.x);
                    v1 = d * (v1 + sv.y);
                    int g16 = col >> 4, lp = (col >> 1) & 7;
                    __half* Ch = (__half*)Cg + (long long)b * sCb;
                    *(__half2*)(Ch + m * ldc + (g16 << 4) + (pos8(lp) << 1)) =
                        __floats2half2_rn(v0, v1);
                } else {  // EPI == 3
                    v0 = fmaf(d, v0 + sv.x, bias[col]);
                    v1 = fmaf(d, v1 + sv.y, bias[col + 1]);
                    float* Cf = (float*)Cg + (long long)b * sCb;
                    *(float2*)(Cf + m * ldc + col) = make_float2(v0, v1);
                }
            }
        }
    }
}

// ===========================================================================
// FUSED feature kernel: per CTA (128 rows m0..m0+127):
//   H = relu(Z1_blk @ W1^T + b1)  -> smem (8 x BK64 operand stages, 128KB)
//   P2acc = H @ W2^T  (K=512 from smem)
//   P2[m][n] = ds[m]*acc (plain fp16) ; P2t[n][m] same, transposed+interleaved
// 512 threads, occ 1, smem 224KB.
// ===========================================================================
static constexpr int FZ1 = 0;               // Z1: 4 stages x 16KB = 64KB
static constexpr int FH  = 65536;           // H : 8 stages x 16KB = 128KB
static constexpr int FWB = 196608;          // W1 stream: 2 x 16KB
static constexpr int FW2 = 0;               // W2 stream: 2 x 32KB (reuses Z1)
static constexpr int FSMEM = 229376;        // 224 KB

__global__ void __launch_bounds__(512, 1) gemm_feat(
    const __half* __restrict__ Z1, const __half* __restrict__ W1t,
    const __half* __restrict__ W2t, const float* __restrict__ b1,
    const float* __restrict__ ds,
    __half* __restrict__ P2t, __half* __restrict__ P2) {

    extern __shared__ char smem[];
    const uint32_t sbase = smem_u32(smem);
    const int tid = threadIdx.x;
    const long long m0 = (long long)blockIdx.x * 128;

    const int warp = tid >> 5, lane = tid & 31;
    const int gr = lane >> 2, t = lane & 3;

    // ---- load Z1 block: 128 rows x 512B into 4 BK64 stages ----
    #pragma unroll
    for (int i = 0; i < 8; i++) {
        int q = tid + i * 512;            // 0..4095 16B-chunks
        int r = q >> 5, c = q & 31;
        const __half* g = Z1 + (m0 + r) * INC + c * 8;
        uint32_t st = c >> 3, cc = c & 7;
        cp_async16(sbase + FZ1 + st * 16384 + r * 128 + ((cc ^ (r & 7)) << 4), g);
    }
    cp_commit();

    // ================= GEMM1: H chunks of 128 hidden =================
    {
        const int mW = (warp >> 2) * 32, nW = (warp & 3) * 32;
        for (int hc = 0; hc < 4; hc++) {
            float acc[2][4][4];
            #pragma unroll
            for (int mi = 0; mi < 2; mi++)
                #pragma unroll
                for (int ni = 0; ni < 4; ni++)
                    #pragma unroll
                    for (int e = 0; e < 4; e++) acc[mi][ni][e] = 0.f;

            auto loadW1 = [&](int buf, int kk) {
                #pragma unroll
                for (int i = 0; i < 2; i++) {
                    int q = tid + i * 512;     // 0..1023 chunks (128 rows x 8)
                    int r = q >> 3, c = q & 7;
                    const __half* g = W1t + (size_t)(hc * 128 + r) * INC + kk * 64 + c * 8;
                    cp_async16(sbase + FWB + buf * 16384 + r * 128 + ((c ^ (r & 7)) << 4), g);
                }
            };
            loadW1(0, 0); cp_commit();

            for (int kk = 0; kk < 4; kk++) {
                if (kk + 1 < 4) { loadW1((kk + 1) & 1, kk + 1); cp_commit(); cp_wait<1>(); }
                else cp_wait<0>();
                __syncthreads();
                uint32_t sa = sbase + FZ1 + kk * 16384;
                uint32_t sb = sbase + FWB + (kk & 1) * 16384;
                #pragma unroll
                for (int G = 0; G < 4; G++) {
                    const int chunk = (G << 1) | (t >> 1);
                    const uint32_t swo = ((chunk ^ gr) << 4) + ((t & 1) << 3);
                    uint32_t a[2][4];
                    #pragma unroll
                    for (int mi = 0; mi < 2; mi++) {
                        uint32_t ra = sa + (mW + mi * 16 + gr) * 128 + swo;
                        lds64(a[mi][0], a[mi][2], ra);
                        lds64(a[mi][1], a[mi][3], ra + 1024);
                    }
                    #pragma unroll
                    for (int ni = 0; ni < 4; ni++) {
                        uint32_t bf[2];
                        lds64(bf[0], bf[1], sb + (nW + ni * 8 + gr) * 128 + swo);
                        #pragma unroll
                        for (int mi = 0; mi < 2; mi++)
                            mma_f16(acc[mi][ni], a[mi], bf);
                    }
                }
                __syncthreads();
            }

            // epilogue hc: relu+bias -> fp16 -> H operand stages
            #pragma unroll
            for (int mi = 0; mi < 2; mi++) {
                #pragma unroll
                for (int rr = 0; rr < 2; rr++) {
                    int m_loc = mW + mi * 16 + gr + rr * 8;
                    #pragma unroll
                    for (int ni = 0; ni < 4; ni++) {
                        int nl = nW + ni * 8 + 2 * t;
                        int h = hc * 128 + nl;
                        float2 bb = *(const float2*)(b1 + h);
                        float v0 = fmaxf(acc[mi][ni][rr * 2 + 0] + bb.x, 0.f);
                        float v1 = fmaxf(acc[mi][ni][rr * 2 + 1] + bb.y, 0.f);
                        __half2 hv = __floats2half2_rn(v0, v1);
                        int sH = h >> 6, k64 = h & 63;
                        int s = (k64 >> 4) * 16 + pos8((k64 >> 1) & 7) * 2;
                        int cch = s >> 3;
                        int win = (2 * s) & 15;
                        uint32_t addr = sbase + FH + sH * 16384 + m_loc * 128
                                      + ((cch ^ (m_loc & 7)) << 4) + win;
                        asm volatile("st.shared.b32 [%0], %1;"
                                     :: "r"(addr), "r"(*(uint32_t*)&hv));
                    }
                }
            }
        }
    }
    __syncthreads();   // H complete; Z1 region free for W2 buffers

    // ================= GEMM2: P2 = H @ W2^T (K=512) =================
    const int mW2 = (warp >> 2) * 32, nW2 = (warp & 3) * 64;
    float acc2[2][8][4];
    #pragma unroll
    for (int mi = 0; mi < 2; mi++)
        #pragma unroll
        for (int ni = 0; ni < 8; ni++)
            #pragma unroll
            for (int e = 0; e < 4; e++) acc2[mi][ni][e] = 0.f;

    auto loadW2 = [&](int buf, int kk) {
        #pragma unroll
        for (int i = 0; i < 4; i++) {
            int q = tid + i * 512;             // 0..2047 chunks (256 rows x 8)
            int r = q >> 3, c = q & 7;
            const __half* g = W2t + (size_t)r * HIDC + kk * 64 + c * 8;
            cp_async16(sbase + FW2 + buf * 32768 + r * 128 + ((c ^ (r & 7)) << 4), g);
        }
    };
    loadW2(0, 0); cp_commit();

    for (int kk = 0; kk < 8; kk++) {
        if (kk + 1 < 8) { loadW2((kk + 1) & 1, kk + 1); cp_commit(); cp_wait<1>(); }
        else cp_wait<0>();
        __syncthreads();
        uint32_t sa = sbase + FH + kk * 16384;
        uint32_t sb = sbase + FW2 + (kk & 1) * 32768;
        #pragma unroll
        for (int G = 0; G < 4; G++) {
            const int chunk = (G << 1) | (t >> 1);
            const uint32_t swo = ((chunk ^ gr) << 4) + ((t & 1) << 3);
            uint32_t a[2][4];
            #pragma unroll
            for (int mi = 0; mi < 2; mi++) {
                uint32_t ra = sa + (mW2 + mi * 16 + gr) * 128 + swo;
                lds64(a[mi][0], a[mi][2], ra);
                lds64(a[mi][1], a[mi][3], ra + 1024);
            }
            #pragma unroll
            for (int ni = 0; ni < 8; ni++) {
                uint32_t bf[2];
                lds64(bf[0], bf[1], sb + (nW2 + ni * 8 + gr) * 128 + swo);
                #pragma unroll
                for (int mi = 0; mi < 2; mi++)
                    mma_f16(acc2[mi][ni], a[mi], bf);
            }
        }
        __syncthreads();
    }

    // ---------------- epilogue: P2 plain + staged transpose for P2t ----------------
    __half* sT = (__half*)(smem + FH);    // [256][136] halfs, reuses H region
    #pragma unroll
    for (int mi = 0; mi < 2; mi++) {
        #pragma unroll
        for (int rr = 0; rr < 2; rr++) {
            int m_loc = mW2 + mi * 16 + gr + rr * 8;
            long long m = m0 + m_loc;
            float d = ds[m];
            #pragma unroll
            for (int ni = 0; ni < 8; ni++) {
                int nl = nW2 + ni * 8 + 2 * t;
                float v0 = d * acc2[mi][ni][rr * 2 + 0];
                float v1 = d * acc2[mi][ni][rr * 2 + 1];
                __half2 hv = __floats2half2_rn(v0, v1);
                *(__half2*)(P2 + m * OUTC + nl) = hv;
                sT[nl * 136 + m_loc] = __low2half(hv);
                sT[(nl + 1) * 136 + m_loc] = __high2half(hv);
            }
        }
    }
    __syncthreads();

    // transposed interleaved writeout: thread = (n, m-half)
    {
        int n = tid & 255, mh = tid >> 8;       // mh in {0,1}
        int b = (int)(m0 >> 12);
        long long m0loc = m0 & 4095;
        __half* Ct = P2t + (size_t)b * OUTC * NNODE + (size_t)n * NNODE + m0loc + mh * 64;
        #pragma unroll
        for (int mg = 0; mg < 4; mg++) {
            __half2 ph[8];
            #pragma unroll
            for (int pp = 0; pp < 8; pp++) {
                int mA = mh * 64 + mg * 16 + 2 * pp;
                ph[pos8(pp)] = __halves2half2(sT[n * 136 + mA], sT[n * 136 + mA + 1]);
            }
            uint4* dst = (uint4*)(Ct + mg * 16);
            dst[0] = *(uint4*)&ph[0];
            dst[1] = *(uint4*)&ph[4];
        }
    }
}

// ---------------------------------------------------------------------------
// launch
// ---------------------------------------------------------------------------
extern "C" void kernel_launch(void* const* d_in, const int* in_sizes, int n_in,
                              void* d_out, int out_size) {
    const float* x  = (const float*)d_in[0];
    const float* A  = (const float*)d_in[1];
    const float* W1 = (const float*)d_in[2];
    const float* b1 = (const float*)d_in[3];
    const float* W2 = (const float*)d_in[4];
    const float* b2 = (const float*)d_in[5];
    float* out = (float*)d_out;

    float* ds;
    __half *Ar, *xs, *xst, *Z1, *P2t, *P2, *W1t, *W2t;
    cudaGetSymbolAddress((void**)&ds,  g_ds);
    cudaGetSymbolAddress((void**)&Ar,  g_Ar);
    cudaGetSymbolAddress((void**)&xs,  g_xs);
    cudaGetSymbolAddress((void**)&xst, g_xst);
    cudaGetSymbolAddress((void**)&Z1,  g_Z1);
    cudaGetSymbolAddress((void**)&P2t, g_P2t);
    cudaGetSymbolAddress((void**)&P2,  g_P2);
    cudaGetSymbolAddress((void**)&W1t, g_W1t);
    cudaGetSymbolAddress((void**)&W2t, g_W2t);

    cudaFuncSetAttribute(gemm_f16_wide<0>, cudaFuncAttributeMaxDynamicSharedMemorySize, WSMEM);
    cudaFuncSetAttribute(gemm_f16_wide<3>, cudaFuncAttributeMaxDynamicSharedMemorySize, WSMEM);
    cudaFuncSetAttribute(gemm_feat,        cudaFuncAttributeMaxDynamicSharedMemorySize, FSMEM);

    // prep
    prep_A_kernel<<<BATCH * NNODE, 256>>>(A, Ar, ds);
    prep_x_kernel<<<dim3(NNODE / 32, INC / 32, BATCH), 256>>>(x, ds, xs, xst);
    prep_W_both<<<512, 256>>>(W1, W2, W1t, W2t);

    // G1: Z1 = ds∘(A@xs + xs)   (wide agg, per-batch, N=256)
    gemm_f16_wide<0><<<dim3(INC / 256, NNODE / 128, BATCH), 256, WSMEM>>>(
        Ar, xst, Z1, xs, ds, nullptr,
        NNODE, NNODE, NNODE, INC, INC,
        (long long)NNODE * NNODE, (long long)INC * NNODE,
        (long long)NNODE * INC, (long long)NNODE * INC);

    // G2+G3 fused: H in smem, P2/P2t out
    gemm_feat<<<MT / 128, 512, FSMEM>>>(Z1, W1t, W2t, b1, ds, P2t, P2);

    // G4: out = ds∘(A@P2 + P2) + b2   (wide agg)
    gemm_f16_wide<3><<<dim3(OUTC / 256, NNODE / 128, BATCH), 256, WSMEM>>>(
        Ar, P2t, out, P2, ds, b2,
        NNODE, NNODE, NNODE, OUTC, OUTC,
        (long long)NNODE * NNODE, (long long)OUTC * NNODE,
        (long long)NNODE * OUTC, (long long)NNODE * OUTC);
}